// round 1
// baseline (speedup 1.0000x reference)
#include <cuda_runtime.h>
#include <math.h>

// Problem constants
#define BB   4
#define TT   4096
#define DD   1024
#define NN   1024
#define BT   16384         // B*T
#define NRAW 4096          // 3N (Wp) + N (W_in) columns in the fused raw buffer
#define NCHUNK 32
#define LCHUNK 128
#define PI_ITERS 400
#define PI_NB 64           // blocks per power-iteration group

// ---------------------------------------------------------------------------
// Device scratch (allocation-free rule: everything is a __device__ global)
// ---------------------------------------------------------------------------
__device__ float g_RAW[(size_t)BT * NRAW];        // 256 MB: [delta_raw|b_raw|c_raw|G] -> later [a|bu|c|y_hat]
__device__ float g_WinT[1024 * 1024];
__device__ float g_WoutT[1024 * 1024];
__device__ float g_AggA[BB * NCHUNK * NN];
__device__ float g_AggB[BB * NCHUNK * NN];
__device__ float g_Z0[BB * NCHUNK * NN];
__device__ float g_v[2][1024];
__device__ float g_yv[2][1024];
__device__ float g_part[2][PI_NB];
__device__ float g_rq[2][PI_NB];
__device__ float g_sigma[2];
__device__ unsigned g_bar_count[2];
__device__ unsigned g_bar_gen[2];

// ---------------------------------------------------------------------------
// Barrier state reset (device globals persist across graph replays)
// ---------------------------------------------------------------------------
__global__ void init_bar_kernel() {
    if (threadIdx.x < 2) {
        g_bar_count[threadIdx.x] = 0u;
        g_bar_gen[threadIdx.x] = 0u;
    }
}

// ---------------------------------------------------------------------------
// 1024x1024 transpose (for the W^T matvec in power iteration)
// ---------------------------------------------------------------------------
__global__ void transpose_1024(const float* __restrict__ in, int which) {
    __shared__ float tile[32][33];
    float* out = which ? g_WoutT : g_WinT;
    int bx = blockIdx.x * 32, by = blockIdx.y * 32;
    int tx = threadIdx.x, ty = threadIdx.y;   // 32x8
    #pragma unroll
    for (int j = 0; j < 32; j += 8)
        tile[ty + j][tx] = in[(size_t)(by + ty + j) * 1024 + bx + tx];
    __syncthreads();
    #pragma unroll
    for (int j = 0; j < 32; j += 8)
        out[(size_t)(bx + ty + j) * 1024 + by + tx] = tile[tx][ty + j];
}

// ---------------------------------------------------------------------------
// Power iteration for top singular value of W (1024x1024), 2 groups.
// Persistent kernel, software grid barrier per group (PI_NB blocks each).
// Cross-block data read with .cg (L1 is not coherent within a launch).
// ---------------------------------------------------------------------------
__device__ __forceinline__ void grid_barrier(int g, unsigned& my_gen) {
    __syncthreads();
    if (threadIdx.x == 0) {
        my_gen++;
        __threadfence();
        unsigned old = atomicAdd(&g_bar_count[g], 1u);
        if (old == (unsigned)(PI_NB - 1)) {
            atomicExch(&g_bar_count[g], 0u);
            __threadfence();
            atomicAdd(&g_bar_gen[g], 1u);
        } else {
            while (*((volatile unsigned*)&g_bar_gen[g]) < my_gen) {}
        }
    }
    __syncthreads();
}

__global__ void __launch_bounds__(256) power_iter_kernel(
    const float* __restrict__ Win, const float* __restrict__ Wout)
{
    int g   = blockIdx.x >> 6;          // 0: W_in, 1: W_out
    int blk = blockIdx.x & 63;
    const float* W  = g ? Wout   : Win;
    const float* WT = g ? g_WoutT : g_WinT;
    int base = blk * 16;                // 16 rows/cols per block
    int tid = threadIdx.x, lane = tid & 31, w = tid >> 5;
    unsigned my_gen = 0;
    __shared__ float s_inv;
    __shared__ float s_pn[8], s_pr[8];

    // init v (deterministic) + its norm partial
    if (tid < 16) {
        int j = base + tid;
        g_v[g][j] = 0.5f + __sinf((float)j * 0.7311f);
    }
    __syncthreads();
    if (tid == 0) {
        float pn = 0.f;
        for (int t = 0; t < 16; t++) { float v = g_v[g][base + t]; pn += v * v; }
        g_part[g][blk] = pn;
    }
    grid_barrier(g, my_gen);

    for (int it = 0; it < PI_ITERS; it++) {
        if (tid == 0) {
            float s = 0.f;
            for (int t = 0; t < PI_NB; t++) s += __ldcg(&g_part[g][t]);
            s_inv = rsqrtf(s);
        }
        __syncthreads();
        float inv = s_inv;

        // y = W * (v * inv): warp w handles rows base+2w, base+2w+1
        #pragma unroll
        for (int rr = 0; rr < 2; rr++) {
            int r = base + w * 2 + rr;
            const float4* Wr = (const float4*)(W + (size_t)r * 1024);
            const float4* V4 = (const float4*)(g_v[g]);
            float s = 0.f;
            #pragma unroll
            for (int j = lane; j < 256; j += 32) {
                float4 a = __ldg(&Wr[j]);
                float4 x = __ldcg(&V4[j]);
                s += a.x * x.x + a.y * x.y + a.z * x.z + a.w * x.w;
            }
            #pragma unroll
            for (int o = 16; o > 0; o >>= 1) s += __shfl_xor_sync(0xffffffffu, s, o);
            if (lane == 0) g_yv[g][r] = s * inv;
        }
        grid_barrier(g, my_gen);

        // v2 = W^T * y (+ norm & Rayleigh partials)
        float pn = 0.f, pr = 0.f;
        #pragma unroll
        for (int rr = 0; rr < 2; rr++) {
            int c = base + w * 2 + rr;
            const float4* Wc = (const float4*)(WT + (size_t)c * 1024);
            const float4* Y4 = (const float4*)(g_yv[g]);
            float s = 0.f;
            #pragma unroll
            for (int j = lane; j < 256; j += 32) {
                float4 a = __ldg(&Wc[j]);
                float4 x = __ldcg(&Y4[j]);
                s += a.x * x.x + a.y * x.y + a.z * x.z + a.w * x.w;
            }
            #pragma unroll
            for (int o = 16; o > 0; o >>= 1) s += __shfl_xor_sync(0xffffffffu, s, o);
            if (lane == 0) {
                float old = __ldcg(&g_v[g][c]);
                g_v[g][c] = s;
                pn += s * s;
                pr += s * old * inv;   // v2 . v_unit  (Rayleigh quotient of W^T W)
            }
        }
        if (lane == 0) { s_pn[w] = pn; s_pr[w] = pr; }
        __syncthreads();
        if (tid == 0) {
            float a = 0.f, b = 0.f;
            for (int t = 0; t < 8; t++) { a += s_pn[t]; b += s_pr[t]; }
            g_part[g][blk] = a;
            g_rq[g][blk] = b;
        }
        grid_barrier(g, my_gen);
    }

    if (blk == 0 && tid == 0) {
        float lam = 0.f;
        for (int t = 0; t < PI_NB; t++) lam += __ldcg(&g_rq[g][t]);
        float sig = sqrtf(fmaxf(lam, 0.f));
        g_sigma[g] = fmaxf(sig, 1.0f);   // scale = max(sigma/1, 1)
    }
}

// ---------------------------------------------------------------------------
// SGEMM (NT): C[M,n] = sum_k A[m,k]*B[n,k].  128x128x16 tiles, 8x8 microtiles.
// MODE 0: A=u (lda 1024), B = [Wp ; W_in] (virtual stack), +bias(bp) for n<3072,
//         C = g_RAW (ldc 4096).
// MODE 1: A = g_RAW+3072 (y_hat slice, lda 4096), B = W_out,
//         C = d_out, scaled by 1/(s_in*s_out).
// ---------------------------------------------------------------------------
template <int MODE>
__global__ void __launch_bounds__(256) sgemm_nt(
    const float* __restrict__ Aparam, int lda,
    const float* __restrict__ B0, const float* __restrict__ B1,
    const float* __restrict__ bias,
    float* __restrict__ Cparam, int ldc)
{
    constexpr int BM = 128, BN = 128, BK = 16, K = 1024;
    __shared__ float As[BK][BM];
    __shared__ float Bs[BK][BN];

    const float* A = (MODE == 0) ? Aparam : (g_RAW + 3072);
    float* C = (MODE == 0) ? g_RAW : Cparam;

    int m0 = blockIdx.y * BM;
    int n0 = blockIdx.x * BN;
    const float* Bp;
    if (MODE == 0) Bp = (n0 < 3072) ? (B0 + (size_t)n0 * K) : (B1 + (size_t)(n0 - 3072) * K);
    else           Bp = B0 + (size_t)n0 * K;
    const float* Ap = A + (size_t)m0 * lda;

    int tid = threadIdx.x;
    int tm = (tid >> 4) * 8;
    int tn = (tid & 15) * 8;

    float acc[8][8];
    #pragma unroll
    for (int i = 0; i < 8; i++)
        #pragma unroll
        for (int j = 0; j < 8; j++) acc[i][j] = 0.f;

    for (int k0 = 0; k0 < K; k0 += BK) {
        #pragma unroll
        for (int L = 0; L < 2; L++) {
            int f = tid + L * 256;          // 512 float4 loads per tile
            int r = f >> 2;
            int c4 = (f & 3) * 4;
            float4 va = *(const float4*)(Ap + (size_t)r * lda + k0 + c4);
            As[c4 + 0][r] = va.x; As[c4 + 1][r] = va.y; As[c4 + 2][r] = va.z; As[c4 + 3][r] = va.w;
            float4 vb = *(const float4*)(Bp + (size_t)r * K + k0 + c4);
            Bs[c4 + 0][r] = vb.x; Bs[c4 + 1][r] = vb.y; Bs[c4 + 2][r] = vb.z; Bs[c4 + 3][r] = vb.w;
        }
        __syncthreads();
        #pragma unroll
        for (int kk = 0; kk < BK; kk++) {
            float4 a0 = *(const float4*)&As[kk][tm];
            float4 a1 = *(const float4*)&As[kk][tm + 4];
            float4 b0 = *(const float4*)&Bs[kk][tn];
            float4 b1 = *(const float4*)&Bs[kk][tn + 4];
            float av[8] = {a0.x, a0.y, a0.z, a0.w, a1.x, a1.y, a1.z, a1.w};
            float bv[8] = {b0.x, b0.y, b0.z, b0.w, b1.x, b1.y, b1.z, b1.w};
            #pragma unroll
            for (int i = 0; i < 8; i++)
                #pragma unroll
                for (int j = 0; j < 8; j++)
                    acc[i][j] = fmaf(av[i], bv[j], acc[i][j]);
        }
        __syncthreads();
    }

    float scale = 1.f;
    if (MODE == 1) scale = 1.f / (g_sigma[0] * g_sigma[1]);
    #pragma unroll
    for (int i = 0; i < 8; i++) {
        size_t crow = (size_t)(m0 + tm + i) * ldc + n0 + tn;
        #pragma unroll
        for (int j = 0; j < 8; j++) {
            float v = acc[i][j];
            if (MODE == 0) {
                int col = n0 + tn + j;
                if (col < 3072) v += __ldg(&bias[col]);
            } else {
                v *= scale;
            }
            C[crow + j] = v;
        }
    }
}

// ---------------------------------------------------------------------------
// Elementwise: raw -> (a, bu, c) in place, with 2x2 spectral normalization
// ---------------------------------------------------------------------------
__device__ __forceinline__ float softplus_f(float x) {
    return fmaxf(x, 0.f) + log1pf(expf(-fabsf(x)));
}

__global__ void __launch_bounds__(256) elementwise_kernel(
    const float* __restrict__ alpha_log, const float* __restrict__ delta_bias,
    const float* __restrict__ log_gamma)
{
    size_t idx = (size_t)blockIdx.x * 256 + threadIdx.x;   // < BT*NN
    int bt = (int)(idx >> 10);
    int i  = (int)(idx & 1023);
    size_t row = (size_t)bt * NRAW;

    float dr  = g_RAW[row + i];
    float brw = g_RAW[row + 1024 + i];
    float crw = g_RAW[row + 2048 + i];
    float gg  = g_RAW[row + 3072 + i];

    float gamma = expf(log_gamma[0]);
    float alpha = softplus_f(alpha_log[i]);
    float delta = softplus_f(dr + delta_bias[i]);
    float a = fminf(expf(-delta * alpha), 1.0f - 1e-4f);
    float b = tanhf(brw);
    float c = tanhf(crw);

    float p = a * a + c * c;
    float r = b * b;
    float q = a * b;
    float d1 = p - r;
    float disc = d1 * d1 + 4.0f * q * q;
    float lam = 0.5f * (p + r + sqrtf(disc + 1e-12f));
    float sg = sqrtf(lam + 1e-12f);
    float inv = 1.0f / fmaxf(sg, 1.0f);
    a *= inv; b *= inv; c *= inv;

    g_RAW[row + i]         = a;
    g_RAW[row + 1024 + i]  = b * gamma * gg;   // bu (s_in deferred)
    g_RAW[row + 2048 + i]  = c;
}

// ---------------------------------------------------------------------------
// Chunked scan: z_{t+1} = a_t z_t + bu_t, z_0 = 0;  y_hat_t = c_t * z_t
// ---------------------------------------------------------------------------
__global__ void __launch_bounds__(128) scan_pass1() {
    int blk = blockIdx.x;                 // 1024 blocks
    int ib = blk & 7;
    int chunk = (blk >> 3) & 31;
    int b = blk >> 8;
    int i = ib * 128 + threadIdx.x;
    size_t base = ((size_t)(b * TT + chunk * LCHUNK)) * NRAW + i;
    float A = 1.f, Bc = 0.f;
    for (int t = 0; t < LCHUNK; t++) {
        size_t o = base + (size_t)t * NRAW;
        float a  = g_RAW[o];
        float bu = g_RAW[o + 1024];
        Bc = fmaf(a, Bc, bu);
        A *= a;
    }
    int ai = (b * NCHUNK + chunk) * NN + i;
    g_AggA[ai] = A;
    g_AggB[ai] = Bc;
}

__global__ void __launch_bounds__(1024) scan_pass2() {
    int ch = blockIdx.x * 1024 + threadIdx.x;   // 4096 channels
    int b = ch >> 10;
    int i = ch & 1023;
    float carry = 0.f;
    for (int c = 0; c < NCHUNK; c++) {
        int ai = (b * NCHUNK + c) * NN + i;
        g_Z0[ai] = carry;
        carry = fmaf(g_AggA[ai], carry, g_AggB[ai]);
    }
}

__global__ void __launch_bounds__(128) scan_pass3() {
    int blk = blockIdx.x;
    int ib = blk & 7;
    int chunk = (blk >> 3) & 31;
    int b = blk >> 8;
    int i = ib * 128 + threadIdx.x;
    size_t base = ((size_t)(b * TT + chunk * LCHUNK)) * NRAW + i;
    float z = g_Z0[(b * NCHUNK + chunk) * NN + i];
    for (int t = 0; t < LCHUNK; t++) {
        size_t o = base + (size_t)t * NRAW;
        float a  = g_RAW[o];
        float bu = g_RAW[o + 1024];
        float c  = g_RAW[o + 2048];
        g_RAW[o + 3072] = c * z;       // y_hat_t = c_t * z_t  (state BEFORE step t)
        z = fmaf(a, z, bu);
    }
}

// ---------------------------------------------------------------------------
// Launch
// ---------------------------------------------------------------------------
extern "C" void kernel_launch(void* const* d_in, const int* in_sizes, int n_in,
                              void* d_out, int out_size)
{
    (void)in_sizes; (void)n_in; (void)out_size;
    const float* u          = (const float*)d_in[0];
    const float* W_in       = (const float*)d_in[1];
    const float* W_out      = (const float*)d_in[2];
    const float* Wp         = (const float*)d_in[3];
    const float* bp         = (const float*)d_in[4];
    const float* alpha_log  = (const float*)d_in[5];
    const float* delta_bias = (const float*)d_in[6];
    const float* log_gamma  = (const float*)d_in[7];
    float* out = (float*)d_out;

    init_bar_kernel<<<1, 32>>>();
    transpose_1024<<<dim3(32, 32), dim3(32, 8)>>>(W_in, 0);
    transpose_1024<<<dim3(32, 32), dim3(32, 8)>>>(W_out, 1);
    power_iter_kernel<<<2 * PI_NB, 256>>>(W_in, W_out);

    // GEMM1: raw = u @ [Wp ; W_in]^T  (+bp on Wp part)
    sgemm_nt<0><<<dim3(NRAW / 128, BT / 128), 256>>>(u, 1024, Wp, W_in, bp, nullptr, NRAW);

    elementwise_kernel<<<(BT * NN) / 256, 256>>>(alpha_log, delta_bias, log_gamma);

    scan_pass1<<<BB * NCHUNK * 8, 128>>>();
    scan_pass2<<<4, 1024>>>();
    scan_pass3<<<BB * NCHUNK * 8, 128>>>();

    // GEMM2: y = y_hat @ W_out^T * 1/(s_in*s_out)
    sgemm_nt<1><<<dim3(NN / 128, BT / 128), 256>>>(nullptr, NRAW, W_out, nullptr, nullptr, out, 1024);
}

// round 3
// speedup vs baseline: 1.2847x; 1.2847x over previous
#include <cuda_runtime.h>
#include <cuda_bf16.h>
#include <math.h>
#include <stdint.h>

// Problem constants
#define BB   4
#define TT   4096
#define NN   1024
#define BT   16384
#define NRAW 4096
#define NCHUNK 32
#define LCHUNK 128
#define PI_ITERS 400
#define PI_NB 64

// GEMM tiling (HMMA mma.sync path; tcgen05 unavailable: harness targets sm_103 w/o 'a')
#define GBM 128
#define GBN 128
#define GBK 64
#define KDIM 1024
#define KCH  16                          // KDIM/GBK
#define STAGE_BYTES 65536                // Ahi16K + Alo16K + Bhi16K + Blo16K
#define SMEM_TOTAL (2*STAGE_BYTES)

// ---------------------------------------------------------------------------
// Device scratch
// ---------------------------------------------------------------------------
__device__ __align__(128) float g_RAW[(size_t)BT * NRAW];
__device__ __align__(128) __nv_bfloat16 g_Ahi[(size_t)BT * KDIM];
__device__ __align__(128) __nv_bfloat16 g_Alo[(size_t)BT * KDIM];
__device__ __align__(128) __nv_bfloat16 g_Bhi[(size_t)NRAW * KDIM];   // [Wp(3072) ; W_in(1024)]
__device__ __align__(128) __nv_bfloat16 g_Blo[(size_t)NRAW * KDIM];
__device__ __align__(128) __nv_bfloat16 g_Whi[(size_t)NN * KDIM];     // W_out
__device__ __align__(128) __nv_bfloat16 g_Wlo[(size_t)NN * KDIM];
__device__ __align__(128) __nv_bfloat16 g_Yhi[(size_t)BT * NN];
__device__ __align__(128) __nv_bfloat16 g_Ylo[(size_t)BT * NN];
__device__ float g_WinT[1024 * 1024];
__device__ float g_WoutT[1024 * 1024];
__device__ float g_AggA[BB * NCHUNK * NN];
__device__ float g_AggB[BB * NCHUNK * NN];
__device__ float g_Z0[BB * NCHUNK * NN];
__device__ float g_v[2][1024];
__device__ float g_yv[2][1024];
__device__ float g_part[2][PI_NB];
__device__ float g_rq[2][PI_NB];
__device__ float g_sigma[2];
__device__ unsigned g_bar_count[2];
__device__ unsigned g_bar_gen[2];

// ---------------------------------------------------------------------------
// PTX helpers
// ---------------------------------------------------------------------------
__device__ __forceinline__ uint32_t smem_u32(const void* p) {
    uint32_t a;
    asm("{ .reg .u64 t; cvta.to.shared.u64 t, %1; cvt.u32.u64 %0, t; }" : "=r"(a) : "l"(p));
    return a;
}

#define CP_ASYNC16(dst, src) \
    asm volatile("cp.async.cg.shared.global [%0], [%1], 16;" :: "r"(dst), "l"(src))
#define CP_COMMIT() asm volatile("cp.async.commit_group;" ::: "memory")
#define CP_WAIT1()  asm volatile("cp.async.wait_group 1;" ::: "memory")
#define CP_WAIT0()  asm volatile("cp.async.wait_group 0;" ::: "memory")

#define LDMATRIX_X4(r0, r1, r2, r3, addr) \
    asm volatile("ldmatrix.sync.aligned.m8n8.x4.shared.b16 {%0,%1,%2,%3}, [%4];" \
                 : "=r"(r0), "=r"(r1), "=r"(r2), "=r"(r3) : "r"(addr))

#define MMA_BF16(d, a, b) \
    asm volatile("mma.sync.aligned.m16n8k16.row.col.f32.bf16.bf16.f32 " \
        "{%0,%1,%2,%3}, {%4,%5,%6,%7}, {%8,%9}, {%0,%1,%2,%3};" \
        : "+f"((d)[0]), "+f"((d)[1]), "+f"((d)[2]), "+f"((d)[3]) \
        : "r"((a)[0]), "r"((a)[1]), "r"((a)[2]), "r"((a)[3]), "r"((b)[0]), "r"((b)[1]))

// ---------------------------------------------------------------------------
// Misc init / transpose
// ---------------------------------------------------------------------------
__global__ void init_bar_kernel() {
    if (threadIdx.x < 2) { g_bar_count[threadIdx.x] = 0u; g_bar_gen[threadIdx.x] = 0u; }
}

__global__ void transpose_1024(const float* __restrict__ in, int which) {
    __shared__ float tile[32][33];
    float* out = which ? g_WoutT : g_WinT;
    int bx = blockIdx.x * 32, by = blockIdx.y * 32;
    int tx = threadIdx.x, ty = threadIdx.y;
    #pragma unroll
    for (int j = 0; j < 32; j += 8)
        tile[ty + j][tx] = in[(size_t)(by + ty + j) * 1024 + bx + tx];
    __syncthreads();
    #pragma unroll
    for (int j = 0; j < 32; j += 8)
        out[(size_t)(bx + ty + j) * 1024 + by + tx] = tile[tx][ty + j];
}

// bf16 hi/lo split.  dst_sel: 0 -> A(u), 1 -> B fused, 2 -> W_out
__global__ void __launch_bounds__(256) split_bf16(const float* __restrict__ src,
                                                  int dst_sel, size_t dst_off, int n4) {
    int i = blockIdx.x * 256 + threadIdx.x;
    if (i >= n4) return;
    __nv_bfloat16* hi; __nv_bfloat16* lo;
    if (dst_sel == 0)      { hi = g_Ahi; lo = g_Alo; }
    else if (dst_sel == 1) { hi = g_Bhi; lo = g_Blo; }
    else                   { hi = g_Whi; lo = g_Wlo; }
    hi += dst_off; lo += dst_off;
    float4 v = ((const float4*)src)[i];
    float x[4] = {v.x, v.y, v.z, v.w};
    union { __nv_bfloat16 b[4]; uint2 u; } H, L;
    #pragma unroll
    for (int j = 0; j < 4; j++) {
        __nv_bfloat16 h = __float2bfloat16(x[j]);
        H.b[j] = h;
        L.b[j] = __float2bfloat16(x[j] - __bfloat162float(h));
    }
    ((uint2*)hi)[i] = H.u;
    ((uint2*)lo)[i] = L.u;
}

// ---------------------------------------------------------------------------
// Power iteration (validated in R1: ~6us, rel_err fine)
// ---------------------------------------------------------------------------
__device__ __forceinline__ void grid_barrier(int g, unsigned& my_gen) {
    __syncthreads();
    if (threadIdx.x == 0) {
        my_gen++;
        __threadfence();
        unsigned old = atomicAdd(&g_bar_count[g], 1u);
        if (old == (unsigned)(PI_NB - 1)) {
            atomicExch(&g_bar_count[g], 0u);
            __threadfence();
            atomicAdd(&g_bar_gen[g], 1u);
        } else {
            while (*((volatile unsigned*)&g_bar_gen[g]) < my_gen) {}
        }
    }
    __syncthreads();
}

__global__ void __launch_bounds__(256) power_iter_kernel(
    const float* __restrict__ Win, const float* __restrict__ Wout)
{
    int g   = blockIdx.x >> 6;
    int blk = blockIdx.x & 63;
    const float* W  = g ? Wout    : Win;
    const float* WT = g ? g_WoutT : g_WinT;
    int base = blk * 16;
    int tid = threadIdx.x, lane = tid & 31, w = tid >> 5;
    unsigned my_gen = 0;
    __shared__ float s_inv;
    __shared__ float s_pn[8], s_pr[8];

    if (tid < 16) {
        int j = base + tid;
        g_v[g][j] = 0.5f + __sinf((float)j * 0.7311f);
    }
    __syncthreads();
    if (tid == 0) {
        float pn = 0.f;
        for (int t = 0; t < 16; t++) { float v = g_v[g][base + t]; pn += v * v; }
        g_part[g][blk] = pn;
    }
    grid_barrier(g, my_gen);

    for (int it = 0; it < PI_ITERS; it++) {
        if (tid == 0) {
            float s = 0.f;
            for (int t = 0; t < PI_NB; t++) s += __ldcg(&g_part[g][t]);
            s_inv = rsqrtf(s);
        }
        __syncthreads();
        float inv = s_inv;

        #pragma unroll
        for (int rr = 0; rr < 2; rr++) {
            int r = base + w * 2 + rr;
            const float4* Wr = (const float4*)(W + (size_t)r * 1024);
            const float4* V4 = (const float4*)(g_v[g]);
            float s = 0.f;
            #pragma unroll
            for (int j = lane; j < 256; j += 32) {
                float4 a = __ldg(&Wr[j]);
                float4 x = __ldcg(&V4[j]);
                s += a.x * x.x + a.y * x.y + a.z * x.z + a.w * x.w;
            }
            #pragma unroll
            for (int o = 16; o > 0; o >>= 1) s += __shfl_xor_sync(0xffffffffu, s, o);
            if (lane == 0) g_yv[g][r] = s * inv;
        }
        grid_barrier(g, my_gen);

        float pn = 0.f, pr = 0.f;
        #pragma unroll
        for (int rr = 0; rr < 2; rr++) {
            int c = base + w * 2 + rr;
            const float4* Wc = (const float4*)(WT + (size_t)c * 1024);
            const float4* Y4 = (const float4*)(g_yv[g]);
            float s = 0.f;
            #pragma unroll
            for (int j = lane; j < 256; j += 32) {
                float4 a = __ldg(&Wc[j]);
                float4 x = __ldcg(&Y4[j]);
                s += a.x * x.x + a.y * x.y + a.z * x.z + a.w * x.w;
            }
            #pragma unroll
            for (int o = 16; o > 0; o >>= 1) s += __shfl_xor_sync(0xffffffffu, s, o);
            if (lane == 0) {
                float old = __ldcg(&g_v[g][c]);
                g_v[g][c] = s;
                pn += s * s;
                pr += s * old * inv;
            }
        }
        if (lane == 0) { s_pn[w] = pn; s_pr[w] = pr; }
        __syncthreads();
        if (tid == 0) {
            float a = 0.f, b = 0.f;
            for (int t = 0; t < 8; t++) { a += s_pn[t]; b += s_pr[t]; }
            g_part[g][blk] = a;
            g_rq[g][blk] = b;
        }
        grid_barrier(g, my_gen);
    }

    if (blk == 0 && tid == 0) {
        float lam = 0.f;
        for (int t = 0; t < PI_NB; t++) lam += __ldcg(&g_rq[g][t]);
        float sig = sqrtf(fmaxf(lam, 0.f));
        g_sigma[g] = fmaxf(sig, 1.0f);
    }
}

// ---------------------------------------------------------------------------
// HMMA GEMM (NT), bf16 hi/lo split: C += Ahi*Bhi + Ahi*Blo + Alo*Bhi.
// 128x128x64 tiles, 8 warps (4m x 2n), warp tile 32x64, m16n8k16.
// MODE 0: A=g_Ahi/lo, B=g_Bhi/lo, C=g_RAW (ldc 4096), +bias for col<3072
// MODE 1: A=g_Yhi/lo, B=g_Whi/lo, C=out (ldc 1024), * 1/(s0*s1)
// ---------------------------------------------------------------------------
__device__ __forceinline__ void load_tiles(
    uint32_t stage_base,
    const __nv_bfloat16* __restrict__ Ah, const __nv_bfloat16* __restrict__ Al,
    const __nv_bfloat16* __restrict__ Bh, const __nv_bfloat16* __restrict__ Bl,
    int tid)
{
    uint32_t sAhi = stage_base, sAlo = stage_base + 16384;
    uint32_t sBhi = stage_base + 32768, sBlo = stage_base + 49152;
    #pragma unroll
    for (int it = 0; it < 4; it++) {               // 128 rows x 8 x 16B
        int c = tid + it * 256;
        int r = c >> 3, c8 = c & 7;
        uint32_t sw = (uint32_t)r * 128 + (((uint32_t)c8 * 16) ^ (((uint32_t)r & 7) << 4));
        CP_ASYNC16(sAhi + sw, (const char*)(Ah + (size_t)r * KDIM) + c8 * 16);
        CP_ASYNC16(sAlo + sw, (const char*)(Al + (size_t)r * KDIM) + c8 * 16);
        CP_ASYNC16(sBhi + sw, (const char*)(Bh + (size_t)r * KDIM) + c8 * 16);
        CP_ASYNC16(sBlo + sw, (const char*)(Bl + (size_t)r * KDIM) + c8 * 16);
    }
}

template <int MODE>
__global__ void __launch_bounds__(256, 1) mma_gemm(
    const float* __restrict__ bias, float* __restrict__ Cout)
{
    extern __shared__ char smem[];
    uint32_t sb = smem_u32(smem);
    int tid = threadIdx.x, wid = tid >> 5, lane = tid & 31;
    int m0 = blockIdx.y * GBM;
    int n0 = blockIdx.x * GBN;
    int wm = wid >> 1, wn = wid & 1;            // 4 x 2 warp grid
    int m_off = wm * 32, n_off = wn * 64;

    const __nv_bfloat16* Ah = (MODE == 0 ? g_Ahi : g_Yhi) + (size_t)m0 * KDIM;
    const __nv_bfloat16* Al = (MODE == 0 ? g_Alo : g_Ylo) + (size_t)m0 * KDIM;
    const __nv_bfloat16* Bh = (MODE == 0 ? g_Bhi : g_Whi) + (size_t)n0 * KDIM;
    const __nv_bfloat16* Bl = (MODE == 0 ? g_Blo : g_Wlo) + (size_t)n0 * KDIM;
    float* C = (MODE == 0) ? g_RAW : Cout;
    const int ldc = (MODE == 0) ? NRAW : NN;

    float acc[2][8][4];
    #pragma unroll
    for (int mt = 0; mt < 2; mt++)
        #pragma unroll
        for (int n = 0; n < 8; n++)
            #pragma unroll
            for (int j = 0; j < 4; j++) acc[mt][n][j] = 0.f;

    // ldmatrix lane addressing: row_in_16tile = lane&15, colByte base = (lane>>4)*16
    int lrow = lane & 15;
    uint32_t lcol = ((uint32_t)(lane >> 4)) << 4;

    load_tiles(sb,               Ah,      Al,      Bh,      Bl,      tid); CP_COMMIT();
    load_tiles(sb + STAGE_BYTES, Ah + 64, Al + 64, Bh + 64, Bl + 64, tid); CP_COMMIT();

    for (int ch = 0; ch < KCH; ch++) {
        int buf = ch & 1;
        if (ch >= KCH - 1) { CP_WAIT0(); } else { CP_WAIT1(); }
        __syncthreads();

        uint32_t base = sb + buf * STAGE_BYTES;
        #pragma unroll
        for (int ks = 0; ks < 4; ks++) {
            uint32_t cb = (uint32_t)ks * 32 + lcol;
            uint32_t ahi[2][4], alo[2][4];
            #pragma unroll
            for (int mt = 0; mt < 2; mt++) {
                int row = m_off + mt * 16 + lrow;
                uint32_t ad = base + (uint32_t)row * 128 + (cb ^ (((uint32_t)row & 7) << 4));
                LDMATRIX_X4(ahi[mt][0], ahi[mt][1], ahi[mt][2], ahi[mt][3], ad);
                LDMATRIX_X4(alo[mt][0], alo[mt][1], alo[mt][2], alo[mt][3], ad + 16384);
            }
            uint32_t bhi[8][2], blo[8][2];
            #pragma unroll
            for (int nt = 0; nt < 4; nt++) {
                int row = n_off + nt * 16 + lrow;
                uint32_t bd = base + 32768 + (uint32_t)row * 128 + (cb ^ (((uint32_t)row & 7) << 4));
                uint32_t r0, r1, r2, r3;
                LDMATRIX_X4(r0, r1, r2, r3, bd);
                bhi[nt * 2][0] = r0; bhi[nt * 2][1] = r2;
                bhi[nt * 2 + 1][0] = r1; bhi[nt * 2 + 1][1] = r3;
                LDMATRIX_X4(r0, r1, r2, r3, bd + 16384);
                blo[nt * 2][0] = r0; blo[nt * 2][1] = r2;
                blo[nt * 2 + 1][0] = r1; blo[nt * 2 + 1][1] = r3;
            }
            #pragma unroll
            for (int mt = 0; mt < 2; mt++)
                #pragma unroll
                for (int n = 0; n < 8; n++) {
                    MMA_BF16(acc[mt][n], ahi[mt], bhi[n]);
                    MMA_BF16(acc[mt][n], ahi[mt], blo[n]);
                    MMA_BF16(acc[mt][n], alo[mt], bhi[n]);
                }
        }
        __syncthreads();
        if (ch + 2 < KCH) {
            int k0 = (ch + 2) * GBK;
            load_tiles(sb + buf * STAGE_BYTES, Ah + k0, Al + k0, Bh + k0, Bl + k0, tid);
            CP_COMMIT();
        }
    }

    float scale = 1.0f;
    if (MODE == 1) scale = 1.0f / (g_sigma[0] * g_sigma[1]);
    int gid = lane >> 2, tig = lane & 3;

    #pragma unroll
    for (int mt = 0; mt < 2; mt++) {
        #pragma unroll
        for (int n = 0; n < 8; n++) {
            int col = n0 + n_off + n * 8 + tig * 2;
            int r0 = m0 + m_off + mt * 16 + gid;
            float2 v0 = make_float2(acc[mt][n][0], acc[mt][n][1]);
            float2 v1 = make_float2(acc[mt][n][2], acc[mt][n][3]);
            if (MODE == 0) {
                if (col < 3072) {
                    float b0 = __ldg(&bias[col]), b1 = __ldg(&bias[col + 1]);
                    v0.x += b0; v0.y += b1; v1.x += b0; v1.y += b1;
                }
            } else {
                v0.x *= scale; v0.y *= scale; v1.x *= scale; v1.y *= scale;
            }
            *(float2*)(C + (size_t)r0 * ldc + col) = v0;
            *(float2*)(C + (size_t)(r0 + 8) * ldc + col) = v1;
        }
    }
}

// ---------------------------------------------------------------------------
// Fused elementwise + scan pass1
// ---------------------------------------------------------------------------
__device__ __forceinline__ float softplus_f(float x) {
    return fmaxf(x, 0.f) + log1pf(expf(-fabsf(x)));
}
__device__ __forceinline__ float tanh_fast(float x) {
    const float L2E2 = 2.8853900817779268f;
    float ax = fabsf(x);
    float e = exp2f(ax * L2E2);
    float r = 1.0f - 2.0f / (e + 1.0f);
    return copysignf(r, x);
}

__global__ void __launch_bounds__(128) ew_scan1(
    const float* __restrict__ alpha_log, const float* __restrict__ delta_bias,
    const float* __restrict__ log_gamma)
{
    const float L2E = 1.4426950408889634f;
    int blk = blockIdx.x;
    int ib = blk & 7;
    int chunk = (blk >> 3) & 31;
    int b = blk >> 8;
    int i = ib * 128 + threadIdx.x;
    size_t base = ((size_t)(b * TT + chunk * LCHUNK)) * NRAW + i;

    float alpha = softplus_f(alpha_log[i]);
    float db    = delta_bias[i];
    float gamma = expf(log_gamma[0]);

    float A = 1.f, Bc = 0.f;
    for (int t = 0; t < LCHUNK; t++) {
        size_t o = base + (size_t)t * NRAW;
        float dr  = g_RAW[o];
        float brw = g_RAW[o + 1024];
        float crw = g_RAW[o + 2048];
        float gg  = g_RAW[o + 3072];

        float s  = dr + db;
        float t1 = exp2f(s * L2E);
        float Lg = log2f(1.0f + t1);
        float a  = exp2f(-alpha * Lg);
        a = fminf(a, 1.0f - 1e-4f);

        float bv = tanh_fast(brw);
        float cv = tanh_fast(crw);

        float p  = a * a + cv * cv;
        float r2 = bv * bv;
        float q  = a * bv;
        float d1 = p - r2;
        float disc = fmaf(d1, d1, 4.0f * q * q) + 1e-12f;
        float sq   = disc * rsqrtf(disc);
        float lam  = 0.5f * (p + r2 + sq) + 1e-12f;
        float inv  = rsqrtf(fmaxf(lam, 1.0f));

        a  *= inv;
        bv *= inv;
        cv *= inv;

        float bu = bv * gamma * gg;
        g_RAW[o]        = a;
        g_RAW[o + 1024] = bu;
        g_RAW[o + 2048] = cv;

        Bc = fmaf(a, Bc, bu);
        A *= a;
    }
    int ai = (b * NCHUNK + chunk) * NN + i;
    g_AggA[ai] = A;
    g_AggB[ai] = Bc;
}

__global__ void __launch_bounds__(1024) scan_pass2() {
    int ch = blockIdx.x * 1024 + threadIdx.x;
    int b = ch >> 10;
    int i = ch & 1023;
    float carry = 0.f;
    for (int c = 0; c < NCHUNK; c++) {
        int ai = (b * NCHUNK + c) * NN + i;
        g_Z0[ai] = carry;
        carry = fmaf(g_AggA[ai], carry, g_AggB[ai]);
    }
}

__global__ void __launch_bounds__(128) scan_pass3() {
    int blk = blockIdx.x;
    int ib = blk & 7;
    int chunk = (blk >> 3) & 31;
    int b = blk >> 8;
    int i = ib * 128 + threadIdx.x;
    int bt0 = b * TT + chunk * LCHUNK;
    size_t base = (size_t)bt0 * NRAW + i;
    float z = g_Z0[(b * NCHUNK + chunk) * NN + i];
    for (int t = 0; t < LCHUNK; t++) {
        size_t o = base + (size_t)t * NRAW;
        float a  = g_RAW[o];
        float bu = g_RAW[o + 1024];
        float c  = g_RAW[o + 2048];
        float y  = c * z;
        size_t yo = (size_t)(bt0 + t) * NN + i;
        __nv_bfloat16 h = __float2bfloat16(y);
        g_Yhi[yo] = h;
        g_Ylo[yo] = __float2bfloat16(y - __bfloat162float(h));
        z = fmaf(a, z, bu);
    }
}

// ---------------------------------------------------------------------------
// Launch
// ---------------------------------------------------------------------------
extern "C" void kernel_launch(void* const* d_in, const int* in_sizes, int n_in,
                              void* d_out, int out_size)
{
    (void)in_sizes; (void)n_in; (void)out_size;
    const float* u          = (const float*)d_in[0];
    const float* W_in       = (const float*)d_in[1];
    const float* W_out      = (const float*)d_in[2];
    const float* Wp         = (const float*)d_in[3];
    const float* bp         = (const float*)d_in[4];
    const float* alpha_log  = (const float*)d_in[5];
    const float* delta_bias = (const float*)d_in[6];
    const float* log_gamma  = (const float*)d_in[7];
    float* out = (float*)d_out;

    cudaFuncSetAttribute(mma_gemm<0>, cudaFuncAttributeMaxDynamicSharedMemorySize, SMEM_TOTAL);
    cudaFuncSetAttribute(mma_gemm<1>, cudaFuncAttributeMaxDynamicSharedMemorySize, SMEM_TOTAL);

    init_bar_kernel<<<1, 32>>>();
    transpose_1024<<<dim3(32, 32), dim3(32, 8)>>>(W_in, 0);
    transpose_1024<<<dim3(32, 32), dim3(32, 8)>>>(W_out, 1);
    power_iter_kernel<<<2 * PI_NB, 256>>>(W_in, W_out);

    split_bf16<<<(BT * KDIM / 4 + 255) / 256, 256>>>(u, 0, 0, BT * KDIM / 4);
    split_bf16<<<(3072 * KDIM / 4 + 255) / 256, 256>>>(Wp, 1, 0, 3072 * KDIM / 4);
    split_bf16<<<(NN * KDIM / 4 + 255) / 256, 256>>>(W_in, 1, (size_t)3072 * KDIM, NN * KDIM / 4);
    split_bf16<<<(NN * KDIM / 4 + 255) / 256, 256>>>(W_out, 2, 0, NN * KDIM / 4);

    // GEMM1: raw = u @ [Wp ; W_in]^T  (+bp on Wp cols)
    mma_gemm<0><<<dim3(NRAW / GBN, BT / GBM), 256, SMEM_TOTAL>>>(bp, nullptr);

    ew_scan1<<<BB * NCHUNK * 8, 128>>>(alpha_log, delta_bias, log_gamma);
    scan_pass2<<<4, 1024>>>();
    scan_pass3<<<BB * NCHUNK * 8, 128>>>();

    // GEMM2: y = y_hat @ W_out^T * 1/(s0*s1)
    mma_gemm<1><<<dim3(NN / GBN, BT / GBM), 256, SMEM_TOTAL>>>(nullptr, out);
}

// round 4
// speedup vs baseline: 4.0872x; 3.1814x over previous
#include <cuda_runtime.h>
#include <cuda_bf16.h>
#include <math.h>
#include <stdint.h>

// Problem constants
#define BB   4
#define TT   4096
#define NN   1024
#define BT   16384
#define NRAW 4096
#define NCHUNK 32
#define LCHUNK 128

// GEMM tiling (HMMA mma.sync path; tcgen05 not available: harness targets sm_103 w/o 'a')
#define GBM 128
#define GBN 128
#define GBK 64
#define KDIM 1024
#define KCH  16                          // KDIM/GBK
#define STAGE_BYTES 65536                // Ahi16K + Alo16K + Bhi16K + Blo16K
#define SMEM_TOTAL (2*STAGE_BYTES)

#define NSQ 9                            // matrix squarings -> G^(2^NSQ)

// ---------------------------------------------------------------------------
// Device scratch
// ---------------------------------------------------------------------------
__device__ __align__(128) float g_RAW[(size_t)BT * NRAW];
__device__ __align__(128) __nv_bfloat16 g_Ahi[(size_t)BT * KDIM];
__device__ __align__(128) __nv_bfloat16 g_Alo[(size_t)BT * KDIM];
__device__ __align__(128) __nv_bfloat16 g_Bhi[(size_t)NRAW * KDIM];   // [Wp(3072) ; W_in(1024)]
__device__ __align__(128) __nv_bfloat16 g_Blo[(size_t)NRAW * KDIM];
__device__ __align__(128) __nv_bfloat16 g_Whi[(size_t)NN * KDIM];     // W_out
__device__ __align__(128) __nv_bfloat16 g_Wlo[(size_t)NN * KDIM];
__device__ __align__(128) __nv_bfloat16 g_Yhi[(size_t)BT * NN];
__device__ __align__(128) __nv_bfloat16 g_Ylo[(size_t)BT * NN];
__device__ float g_WinT[1024 * 1024];
__device__ float g_WoutT[1024 * 1024];
__device__ float g_AggA[BB * NCHUNK * NN];
__device__ float g_AggB[BB * NCHUNK * NN];
__device__ float g_Z0[BB * NCHUNK * NN];

// spectral-norm machinery
__device__ __align__(128) __nv_bfloat16 g_Shi[1024 * 1024];
__device__ __align__(128) __nv_bfloat16 g_Slo[1024 * 1024];
__device__ __align__(128) float g_Gk[1024 * 1024];   // current squared matrix (fp32)
__device__ __align__(128) float g_G0[1024 * 1024];   // original G = W^T W (fp32)
__device__ float g_pv[1024];
__device__ float g_pw[1024];
__device__ float g_trace[16];
__device__ float g_acc;
__device__ float g_sigma[2];

// ---------------------------------------------------------------------------
// PTX helpers
// ---------------------------------------------------------------------------
__device__ __forceinline__ uint32_t smem_u32(const void* p) {
    uint32_t a;
    asm("{ .reg .u64 t; cvta.to.shared.u64 t, %1; cvt.u32.u64 %0, t; }" : "=r"(a) : "l"(p));
    return a;
}

#define CP_ASYNC16(dst, src) \
    asm volatile("cp.async.cg.shared.global [%0], [%1], 16;" :: "r"(dst), "l"(src))
#define CP_COMMIT() asm volatile("cp.async.commit_group;" ::: "memory")
#define CP_WAIT1()  asm volatile("cp.async.wait_group 1;" ::: "memory")
#define CP_WAIT0()  asm volatile("cp.async.wait_group 0;" ::: "memory")

#define LDMATRIX_X4(r0, r1, r2, r3, addr) \
    asm volatile("ldmatrix.sync.aligned.m8n8.x4.shared.b16 {%0,%1,%2,%3}, [%4];" \
                 : "=r"(r0), "=r"(r1), "=r"(r2), "=r"(r3) : "r"(addr))

#define MMA_BF16(d, a, b) \
    asm volatile("mma.sync.aligned.m16n8k16.row.col.f32.bf16.bf16.f32 " \
        "{%0,%1,%2,%3}, {%4,%5,%6,%7}, {%8,%9}, {%0,%1,%2,%3};" \
        : "+f"((d)[0]), "+f"((d)[1]), "+f"((d)[2]), "+f"((d)[3]) \
        : "r"((a)[0]), "r"((a)[1]), "r"((a)[2]), "r"((a)[3]), "r"((b)[0]), "r"((b)[1]))

// ---------------------------------------------------------------------------
// Transpose (W -> W^T, fp32)
// ---------------------------------------------------------------------------
__global__ void transpose_1024(const float* __restrict__ in, int which) {
    __shared__ float tile[32][33];
    float* out = which ? g_WoutT : g_WinT;
    int bx = blockIdx.x * 32, by = blockIdx.y * 32;
    int tx = threadIdx.x, ty = threadIdx.y;
    #pragma unroll
    for (int j = 0; j < 32; j += 8)
        tile[ty + j][tx] = in[(size_t)(by + ty + j) * 1024 + bx + tx];
    __syncthreads();
    #pragma unroll
    for (int j = 0; j < 32; j += 8)
        out[(size_t)(bx + ty + j) * 1024 + by + tx] = tile[tx][ty + j];
}

// ---------------------------------------------------------------------------
// bf16 hi/lo splits
// ---------------------------------------------------------------------------
__device__ __forceinline__ void split4(const float4 v, uint2& H, uint2& L) {
    union { __nv_bfloat16 b[4]; uint2 u; } h, l;
    float x[4] = {v.x, v.y, v.z, v.w};
    #pragma unroll
    for (int j = 0; j < 4; j++) {
        __nv_bfloat16 hb = __float2bfloat16(x[j]);
        h.b[j] = hb;
        l.b[j] = __float2bfloat16(x[j] - __bfloat162float(hb));
    }
    H = h.u; L = l.u;
}

// dst_sel: 0 -> A(u), 1 -> B fused, 2 -> W_out
__global__ void __launch_bounds__(256) split_bf16(const float* __restrict__ src,
                                                  int dst_sel, size_t dst_off, int n4) {
    int i = blockIdx.x * 256 + threadIdx.x;
    if (i >= n4) return;
    __nv_bfloat16* hi; __nv_bfloat16* lo;
    if (dst_sel == 0)      { hi = g_Ahi; lo = g_Alo; }
    else if (dst_sel == 1) { hi = g_Bhi; lo = g_Blo; }
    else                   { hi = g_Whi; lo = g_Wlo; }
    hi += dst_off; lo += dst_off;
    uint2 H, L;
    split4(((const float4*)src)[i], H, L);
    ((uint2*)hi)[i] = H;
    ((uint2*)lo)[i] = L;
}

// W^T (fp32 device global) -> g_Shi/g_Slo
__global__ void __launch_bounds__(256) split_WT(int which) {
    int i = blockIdx.x * 256 + threadIdx.x;          // < 1024*1024/4
    const float* src = which ? g_WoutT : g_WinT;
    uint2 H, L;
    split4(((const float4*)src)[i], H, L);
    ((uint2*)g_Shi)[i] = H;
    ((uint2*)g_Slo)[i] = L;
}

// g_Gk * (1024/trace[step]) -> g_Shi/g_Slo
__global__ void __launch_bounds__(256) split_scaled(int step) {
    int i = blockIdx.x * 256 + threadIdx.x;
    float s = 1024.0f / g_trace[step];
    float4 v = ((const float4*)g_Gk)[i];
    v.x *= s; v.y *= s; v.z *= s; v.w *= s;
    uint2 H, L;
    split4(v, H, L);
    ((uint2*)g_Shi)[i] = H;
    ((uint2*)g_Slo)[i] = L;
}

__global__ void __launch_bounds__(256) copy_G0() {
    int i = blockIdx.x * 256 + threadIdx.x;
    ((float4*)g_G0)[i] = ((const float4*)g_Gk)[i];
}

__global__ void __launch_bounds__(1024) init_spec() {
    int t = threadIdx.x;
    g_pv[t] = 0.5f + __sinf((float)t * 0.7311f);
    if (t < 16) g_trace[t] = 0.f;
    if (t == 0) g_acc = 0.f;
}

// ---------------------------------------------------------------------------
// Small matvec helpers (64 blocks x 256 thr, warp handles 2 rows)
// ---------------------------------------------------------------------------
__global__ void __launch_bounds__(256) mv_kernel() {
    int w = threadIdx.x >> 5, lane = threadIdx.x & 31;
    #pragma unroll
    for (int rr = 0; rr < 2; rr++) {
        int r = blockIdx.x * 16 + w * 2 + rr;
        const float4* Gr = (const float4*)(g_Gk + (size_t)r * 1024);
        const float4* V4 = (const float4*)g_pv;
        float s = 0.f;
        #pragma unroll 4
        for (int j = lane; j < 256; j += 32) {
            float4 a = Gr[j], x = V4[j];
            s += a.x * x.x + a.y * x.y + a.z * x.z + a.w * x.w;
        }
        #pragma unroll
        for (int o = 16; o > 0; o >>= 1) s += __shfl_xor_sync(0xffffffffu, s, o);
        if (lane == 0) g_pw[r] = s;
    }
}

__global__ void __launch_bounds__(1024) vnorm_kernel() {
    __shared__ float sp[32];
    int t = threadIdx.x, lane = t & 31, w = t >> 5;
    float v = g_pw[t];
    float p = v * v;
    #pragma unroll
    for (int o = 16; o > 0; o >>= 1) p += __shfl_xor_sync(0xffffffffu, p, o);
    if (lane == 0) sp[w] = p;
    __syncthreads();
    if (w == 0) {
        float q = (lane < 32) ? sp[lane] : 0.f;
        #pragma unroll
        for (int o = 16; o > 0; o >>= 1) q += __shfl_xor_sync(0xffffffffu, q, o);
        if (lane == 0) sp[0] = rsqrtf(q);
    }
    __syncthreads();
    g_pv[t] = v * sp[0];
}

// Rayleigh quotient num = v^T G0 v  (v unit) -> g_acc
__global__ void __launch_bounds__(256) rq_kernel() {
    int w = threadIdx.x >> 5, lane = threadIdx.x & 31;
    float part = 0.f;
    #pragma unroll
    for (int rr = 0; rr < 2; rr++) {
        int r = blockIdx.x * 16 + w * 2 + rr;
        const float4* Gr = (const float4*)(g_G0 + (size_t)r * 1024);
        const float4* V4 = (const float4*)g_pv;
        float s = 0.f;
        #pragma unroll 4
        for (int j = lane; j < 256; j += 32) {
            float4 a = Gr[j], x = V4[j];
            s += a.x * x.x + a.y * x.y + a.z * x.z + a.w * x.w;
        }
        #pragma unroll
        for (int o = 16; o > 0; o >>= 1) s += __shfl_xor_sync(0xffffffffu, s, o);
        if (lane == 0) part += s * g_pv[r];
    }
    if (lane == 0) atomicAdd(&g_acc, part);
}

__global__ void fin_sigma(int g) {
    g_sigma[g] = fmaxf(1.0f, sqrtf(fmaxf(g_acc, 0.f)));
}

// ---------------------------------------------------------------------------
// HMMA GEMM (NT), bf16 hi/lo split: C += Ahi*Bhi + Ahi*Blo + Alo*Bhi.
// 128x128x64 tiles, 8 warps (4m x 2n), warp tile 32x64, m16n8k16.
// MODE 0: A=g_Ahi/lo, B=g_Bhi/lo, C=g_RAW (ldc 4096), +bias for col<3072
// MODE 1: A=g_Yhi/lo, B=g_Whi/lo, C=out (ldc 1024), * 1/(s0*s1)
// MODE 2: A=B=g_Shi/lo, C=g_Gk (ldc 1024), accumulate trace into g_trace[step]
// ---------------------------------------------------------------------------
__device__ __forceinline__ void load_tiles(
    uint32_t stage_base,
    const __nv_bfloat16* __restrict__ Ah, const __nv_bfloat16* __restrict__ Al,
    const __nv_bfloat16* __restrict__ Bh, const __nv_bfloat16* __restrict__ Bl,
    int tid)
{
    uint32_t sAhi = stage_base, sAlo = stage_base + 16384;
    uint32_t sBhi = stage_base + 32768, sBlo = stage_base + 49152;
    #pragma unroll
    for (int it = 0; it < 4; it++) {               // 128 rows x 8 x 16B
        int c = tid + it * 256;
        int r = c >> 3, c8 = c & 7;
        uint32_t sw = (uint32_t)r * 128 + (((uint32_t)c8 * 16) ^ (((uint32_t)r & 7) << 4));
        CP_ASYNC16(sAhi + sw, (const char*)(Ah + (size_t)r * KDIM) + c8 * 16);
        CP_ASYNC16(sAlo + sw, (const char*)(Al + (size_t)r * KDIM) + c8 * 16);
        CP_ASYNC16(sBhi + sw, (const char*)(Bh + (size_t)r * KDIM) + c8 * 16);
        CP_ASYNC16(sBlo + sw, (const char*)(Bl + (size_t)r * KDIM) + c8 * 16);
    }
}

template <int MODE>
__global__ void __launch_bounds__(256, 1) mma_gemm(
    const float* __restrict__ bias, float* __restrict__ Cout, int step)
{
    extern __shared__ char smem[];
    uint32_t sb = smem_u32(smem);
    int tid = threadIdx.x, wid = tid >> 5, lane = tid & 31;
    int m0 = blockIdx.y * GBM;
    int n0 = blockIdx.x * GBN;
    int wm = wid >> 1, wn = wid & 1;            // 4 x 2 warp grid
    int m_off = wm * 32, n_off = wn * 64;

    const __nv_bfloat16* Ah = (MODE == 0 ? g_Ahi : MODE == 1 ? g_Yhi : g_Shi) + (size_t)m0 * KDIM;
    const __nv_bfloat16* Al = (MODE == 0 ? g_Alo : MODE == 1 ? g_Ylo : g_Slo) + (size_t)m0 * KDIM;
    const __nv_bfloat16* Bh = (MODE == 0 ? g_Bhi : MODE == 1 ? g_Whi : g_Shi) + (size_t)n0 * KDIM;
    const __nv_bfloat16* Bl = (MODE == 0 ? g_Blo : MODE == 1 ? g_Wlo : g_Slo) + (size_t)n0 * KDIM;
    float* C = (MODE == 0) ? g_RAW : (MODE == 1) ? Cout : g_Gk;
    const int ldc = (MODE == 0) ? NRAW : NN;

    float acc[2][8][4];
    #pragma unroll
    for (int mt = 0; mt < 2; mt++)
        #pragma unroll
        for (int n = 0; n < 8; n++)
            #pragma unroll
            for (int j = 0; j < 4; j++) acc[mt][n][j] = 0.f;

    int lrow = lane & 15;
    uint32_t lcol = ((uint32_t)(lane >> 4)) << 4;

    load_tiles(sb,               Ah,      Al,      Bh,      Bl,      tid); CP_COMMIT();
    load_tiles(sb + STAGE_BYTES, Ah + 64, Al + 64, Bh + 64, Bl + 64, tid); CP_COMMIT();

    for (int ch = 0; ch < KCH; ch++) {
        int buf = ch & 1;
        if (ch >= KCH - 1) { CP_WAIT0(); } else { CP_WAIT1(); }
        __syncthreads();

        uint32_t base = sb + buf * STAGE_BYTES;
        #pragma unroll
        for (int ks = 0; ks < 4; ks++) {
            uint32_t cb = (uint32_t)ks * 32 + lcol;
            uint32_t ahi[2][4], alo[2][4];
            #pragma unroll
            for (int mt = 0; mt < 2; mt++) {
                int row = m_off + mt * 16 + lrow;
                uint32_t ad = base + (uint32_t)row * 128 + (cb ^ (((uint32_t)row & 7) << 4));
                LDMATRIX_X4(ahi[mt][0], ahi[mt][1], ahi[mt][2], ahi[mt][3], ad);
                LDMATRIX_X4(alo[mt][0], alo[mt][1], alo[mt][2], alo[mt][3], ad + 16384);
            }
            uint32_t bhi[8][2], blo[8][2];
            #pragma unroll
            for (int nt = 0; nt < 4; nt++) {
                int row = n_off + nt * 16 + lrow;
                uint32_t bd = base + 32768 + (uint32_t)row * 128 + (cb ^ (((uint32_t)row & 7) << 4));
                uint32_t r0, r1, r2, r3;
                LDMATRIX_X4(r0, r1, r2, r3, bd);
                bhi[nt * 2][0] = r0; bhi[nt * 2][1] = r2;
                bhi[nt * 2 + 1][0] = r1; bhi[nt * 2 + 1][1] = r3;
                LDMATRIX_X4(r0, r1, r2, r3, bd + 16384);
                blo[nt * 2][0] = r0; blo[nt * 2][1] = r2;
                blo[nt * 2 + 1][0] = r1; blo[nt * 2 + 1][1] = r3;
            }
            #pragma unroll
            for (int mt = 0; mt < 2; mt++)
                #pragma unroll
                for (int n = 0; n < 8; n++) {
                    MMA_BF16(acc[mt][n], ahi[mt], bhi[n]);
                    MMA_BF16(acc[mt][n], ahi[mt], blo[n]);
                    MMA_BF16(acc[mt][n], alo[mt], bhi[n]);
                }
        }
        __syncthreads();
        if (ch + 2 < KCH) {
            int k0 = (ch + 2) * GBK;
            load_tiles(sb + buf * STAGE_BYTES, Ah + k0, Al + k0, Bh + k0, Bl + k0, tid);
            CP_COMMIT();
        }
    }

    float scale = 1.0f;
    if (MODE == 1) scale = 1.0f / (g_sigma[0] * g_sigma[1]);
    int gid = lane >> 2, tig = lane & 3;
    float tp = 0.f;

    #pragma unroll
    for (int mt = 0; mt < 2; mt++) {
        #pragma unroll
        for (int n = 0; n < 8; n++) {
            int col = n0 + n_off + n * 8 + tig * 2;
            int r0 = m0 + m_off + mt * 16 + gid;
            float2 v0 = make_float2(acc[mt][n][0], acc[mt][n][1]);
            float2 v1 = make_float2(acc[mt][n][2], acc[mt][n][3]);
            if (MODE == 0) {
                if (col < 3072) {
                    float b0 = __ldg(&bias[col]), b1 = __ldg(&bias[col + 1]);
                    v0.x += b0; v0.y += b1; v1.x += b0; v1.y += b1;
                }
            } else if (MODE == 1) {
                v0.x *= scale; v0.y *= scale; v1.x *= scale; v1.y *= scale;
            } else {
                if (r0 == col)     tp += v0.x;
                if (r0 == col + 1) tp += v0.y;
                if (r0 + 8 == col)     tp += v1.x;
                if (r0 + 8 == col + 1) tp += v1.y;
            }
            *(float2*)(C + (size_t)r0 * ldc + col) = v0;
            *(float2*)(C + (size_t)(r0 + 8) * ldc + col) = v1;
        }
    }
    if (MODE == 2 && m0 == n0 && tp != 0.f) atomicAdd(&g_trace[step], tp);
    if (MODE == 2 && m0 == n0 && tid == 0) atomicAdd(&g_trace[step], 0.f);  // keep slot touched
}

// ---------------------------------------------------------------------------
// Fused elementwise + scan pass1
// ---------------------------------------------------------------------------
__device__ __forceinline__ float softplus_f(float x) {
    return fmaxf(x, 0.f) + log1pf(expf(-fabsf(x)));
}
__device__ __forceinline__ float tanh_fast(float x) {
    const float L2E2 = 2.8853900817779268f;
    float ax = fabsf(x);
    float e = exp2f(ax * L2E2);
    float r = 1.0f - 2.0f / (e + 1.0f);
    return copysignf(r, x);
}

__global__ void __launch_bounds__(128) ew_scan1(
    const float* __restrict__ alpha_log, const float* __restrict__ delta_bias,
    const float* __restrict__ log_gamma)
{
    const float L2E = 1.4426950408889634f;
    int blk = blockIdx.x;
    int ib = blk & 7;
    int chunk = (blk >> 3) & 31;
    int b = blk >> 8;
    int i = ib * 128 + threadIdx.x;
    size_t base = ((size_t)(b * TT + chunk * LCHUNK)) * NRAW + i;

    float alpha = softplus_f(alpha_log[i]);
    float db    = delta_bias[i];
    float gamma = expf(log_gamma[0]);

    float A = 1.f, Bc = 0.f;
    for (int t = 0; t < LCHUNK; t++) {
        size_t o = base + (size_t)t * NRAW;
        float dr  = g_RAW[o];
        float brw = g_RAW[o + 1024];
        float crw = g_RAW[o + 2048];
        float gg  = g_RAW[o + 3072];

        float s  = dr + db;
        float t1 = exp2f(s * L2E);
        float Lg = log2f(1.0f + t1);
        float a  = exp2f(-alpha * Lg);
        a = fminf(a, 1.0f - 1e-4f);

        float bv = tanh_fast(brw);
        float cv = tanh_fast(crw);

        float p  = a * a + cv * cv;
        float r2 = bv * bv;
        float q  = a * bv;
        float d1 = p - r2;
        float disc = fmaf(d1, d1, 4.0f * q * q) + 1e-12f;
        float sq   = disc * rsqrtf(disc);
        float lam  = 0.5f * (p + r2 + sq) + 1e-12f;
        float inv  = rsqrtf(fmaxf(lam, 1.0f));

        a  *= inv;
        bv *= inv;
        cv *= inv;

        float bu = bv * gamma * gg;
        g_RAW[o]        = a;
        g_RAW[o + 1024] = bu;
        g_RAW[o + 2048] = cv;

        Bc = fmaf(a, Bc, bu);
        A *= a;
    }
    int ai = (b * NCHUNK + chunk) * NN + i;
    g_AggA[ai] = A;
    g_AggB[ai] = Bc;
}

__global__ void __launch_bounds__(1024) scan_pass2() {
    int ch = blockIdx.x * 1024 + threadIdx.x;
    int b = ch >> 10;
    int i = ch & 1023;
    float carry = 0.f;
    for (int c = 0; c < NCHUNK; c++) {
        int ai = (b * NCHUNK + c) * NN + i;
        g_Z0[ai] = carry;
        carry = fmaf(g_AggA[ai], carry, g_AggB[ai]);
    }
}

__global__ void __launch_bounds__(128) scan_pass3() {
    int blk = blockIdx.x;
    int ib = blk & 7;
    int chunk = (blk >> 3) & 31;
    int b = blk >> 8;
    int i = ib * 128 + threadIdx.x;
    int bt0 = b * TT + chunk * LCHUNK;
    size_t base = (size_t)bt0 * NRAW + i;
    float z = g_Z0[(b * NCHUNK + chunk) * NN + i];
    for (int t = 0; t < LCHUNK; t++) {
        size_t o = base + (size_t)t * NRAW;
        float a  = g_RAW[o];
        float bu = g_RAW[o + 1024];
        float c  = g_RAW[o + 2048];
        float y  = c * z;
        size_t yo = (size_t)(bt0 + t) * NN + i;
        __nv_bfloat16 h = __float2bfloat16(y);
        g_Yhi[yo] = h;
        g_Ylo[yo] = __float2bfloat16(y - __bfloat162float(h));
        z = fmaf(a, z, bu);
    }
}

// ---------------------------------------------------------------------------
// Launch
// ---------------------------------------------------------------------------
extern "C" void kernel_launch(void* const* d_in, const int* in_sizes, int n_in,
                              void* d_out, int out_size)
{
    (void)in_sizes; (void)n_in; (void)out_size;
    const float* u          = (const float*)d_in[0];
    const float* W_in       = (const float*)d_in[1];
    const float* W_out      = (const float*)d_in[2];
    const float* Wp         = (const float*)d_in[3];
    const float* bp         = (const float*)d_in[4];
    const float* alpha_log  = (const float*)d_in[5];
    const float* delta_bias = (const float*)d_in[6];
    const float* log_gamma  = (const float*)d_in[7];
    float* out = (float*)d_out;

    cudaFuncSetAttribute(mma_gemm<0>, cudaFuncAttributeMaxDynamicSharedMemorySize, SMEM_TOTAL);
    cudaFuncSetAttribute(mma_gemm<1>, cudaFuncAttributeMaxDynamicSharedMemorySize, SMEM_TOTAL);
    cudaFuncSetAttribute(mma_gemm<2>, cudaFuncAttributeMaxDynamicSharedMemorySize, SMEM_TOTAL);

    const dim3 gsq(1024 / GBN, 1024 / GBM);     // 8x8 for squaring GEMMs
    const int b1k = (1024 * 1024 / 4) / 256;    // 1024 blocks for 1M-elem fp32 ops

    // ---- spectral norms via repeated squaring + Rayleigh quotient ----
    for (int g = 0; g < 2; g++) {
        const float* W = g ? W_out : W_in;
        transpose_1024<<<dim3(32, 32), dim3(32, 8)>>>(W, g);
        init_spec<<<1, 1024>>>();
        split_WT<<<b1k, 256>>>(g);
        mma_gemm<2><<<gsq, 256, SMEM_TOTAL>>>(nullptr, nullptr, 0);    // G0 = W^T W
        copy_G0<<<b1k, 256>>>();
        for (int k = 1; k <= NSQ; k++) {
            split_scaled<<<b1k, 256>>>(k - 1);
            mma_gemm<2><<<gsq, 256, SMEM_TOTAL>>>(nullptr, nullptr, k);
        }
        for (int r = 0; r < 3; r++) {
            mv_kernel<<<64, 256>>>();
            vnorm_kernel<<<1, 1024>>>();
        }
        rq_kernel<<<64, 256>>>();
        fin_sigma<<<1, 1>>>(g);
    }

    // ---- main path ----
    split_bf16<<<(BT * KDIM / 4 + 255) / 256, 256>>>(u, 0, 0, BT * KDIM / 4);
    split_bf16<<<(3072 * KDIM / 4 + 255) / 256, 256>>>(Wp, 1, 0, 3072 * KDIM / 4);
    split_bf16<<<(NN * KDIM / 4 + 255) / 256, 256>>>(W_in, 1, (size_t)3072 * KDIM, NN * KDIM / 4);
    split_bf16<<<(NN * KDIM / 4 + 255) / 256, 256>>>(W_out, 2, 0, NN * KDIM / 4);

    // GEMM1: raw = u @ [Wp ; W_in]^T  (+bp on Wp cols)
    mma_gemm<0><<<dim3(NRAW / GBN, BT / GBM), 256, SMEM_TOTAL>>>(bp, nullptr, 0);

    ew_scan1<<<BB * NCHUNK * 8, 128>>>(alpha_log, delta_bias, log_gamma);
    scan_pass2<<<4, 1024>>>();
    scan_pass3<<<BB * NCHUNK * 8, 128>>>();

    // GEMM2: y = y_hat @ W_out^T * 1/(s0*s1)
    mma_gemm<1><<<dim3(NN / GBN, BT / GBM), 256, SMEM_TOTAL>>>(nullptr, out, 0);
}

// round 5
// speedup vs baseline: 5.0085x; 1.2254x over previous
#include <cuda_runtime.h>
#include <cuda_bf16.h>
#include <math.h>
#include <stdint.h>

// Problem constants
#define BB   4
#define TT   4096
#define NN   1024
#define BT   16384
#define NRAW 4096
#define NCHUNK 32
#define LCHUNK 128

// GEMM tiling (HMMA mma.sync; tcgen05 unavailable: harness targets sm_103 w/o 'a')
#define GBN 128
#define GBK 64
#define KDIM 1024
#define KCH  16                          // KDIM/GBK

#define NSQ 8                            // squarings -> G^(2^NSQ)
#define NMV 4                            // chained matvecs

#define SM128 196608                     // 3 * (2*16384 + 32768)
#define SM64  147456                     // 3 * (2*8192  + 32768)

// ---------------------------------------------------------------------------
// Device scratch
// ---------------------------------------------------------------------------
__device__ __align__(128) float g_RAW[(size_t)BT * NRAW];
__device__ __align__(128) __nv_bfloat16 g_Ahi[(size_t)BT * KDIM];
__device__ __align__(128) __nv_bfloat16 g_Alo[(size_t)BT * KDIM];
__device__ __align__(128) __nv_bfloat16 g_Bhi[(size_t)NRAW * KDIM];   // [Wp(3072) ; W_in(1024)]
__device__ __align__(128) __nv_bfloat16 g_Blo[(size_t)NRAW * KDIM];
__device__ __align__(128) __nv_bfloat16 g_Whi[(size_t)NN * KDIM];     // W_out
__device__ __align__(128) __nv_bfloat16 g_Wlo[(size_t)NN * KDIM];
__device__ __align__(128) __nv_bfloat16 g_Yhi[(size_t)BT * NN];
__device__ __align__(128) __nv_bfloat16 g_Ylo[(size_t)BT * NN];
__device__ float g_AggA[BB * NCHUNK * NN];
__device__ float g_AggB[BB * NCHUNK * NN];
__device__ float g_Z0[BB * NCHUNK * NN];

// spectral-norm machinery (batched over both weights, index g in {0,1})
__device__ __align__(128) __nv_bfloat16 g_Shi[2 * 1024 * 1024];
__device__ __align__(128) __nv_bfloat16 g_Slo[2 * 1024 * 1024];
__device__ __align__(128) float g_Gk[2 * 1024 * 1024];
__device__ __align__(128) float g_G0[2 * 1024 * 1024];
__device__ float g_pv[2 * 1024];
__device__ float g_pw[2 * 1024];
__device__ float g_trace[32];            // [g*16 + step]
__device__ float g_acc[2];
__device__ float g_sigma[2];

// ---------------------------------------------------------------------------
// PTX helpers
// ---------------------------------------------------------------------------
__device__ __forceinline__ uint32_t smem_u32(const void* p) {
    uint32_t a;
    asm("{ .reg .u64 t; cvta.to.shared.u64 t, %1; cvt.u32.u64 %0, t; }" : "=r"(a) : "l"(p));
    return a;
}

#define CP_ASYNC16(dst, src) \
    asm volatile("cp.async.cg.shared.global [%0], [%1], 16;" :: "r"(dst), "l"(src))
#define CP_COMMIT() asm volatile("cp.async.commit_group;" ::: "memory")
#define CP_WAIT1()  asm volatile("cp.async.wait_group 1;" ::: "memory")
#define CP_WAIT0()  asm volatile("cp.async.wait_group 0;" ::: "memory")

#define LDMATRIX_X4(r0, r1, r2, r3, addr) \
    asm volatile("ldmatrix.sync.aligned.m8n8.x4.shared.b16 {%0,%1,%2,%3}, [%4];" \
                 : "=r"(r0), "=r"(r1), "=r"(r2), "=r"(r3) : "r"(addr))

#define MMA_BF16(d, a, b) \
    asm volatile("mma.sync.aligned.m16n8k16.row.col.f32.bf16.bf16.f32 " \
        "{%0,%1,%2,%3}, {%4,%5,%6,%7}, {%8,%9}, {%0,%1,%2,%3};" \
        : "+f"((d)[0]), "+f"((d)[1]), "+f"((d)[2]), "+f"((d)[3]) \
        : "r"((a)[0]), "r"((a)[1]), "r"((a)[2]), "r"((a)[3]), "r"((b)[0]), "r"((b)[1]))

// ---------------------------------------------------------------------------
// bf16 hi/lo split helpers
// ---------------------------------------------------------------------------
__device__ __forceinline__ void split4(const float4 v, uint2& H, uint2& L) {
    union { __nv_bfloat16 b[4]; uint2 u; } h, l;
    float x[4] = {v.x, v.y, v.z, v.w};
    #pragma unroll
    for (int j = 0; j < 4; j++) {
        __nv_bfloat16 hb = __float2bfloat16(x[j]);
        h.b[j] = hb;
        l.b[j] = __float2bfloat16(x[j] - __bfloat162float(hb));
    }
    H = h.u; L = l.u;
}

// dst_sel: 0 -> A(u), 1 -> B fused, 2 -> W_out
__global__ void __launch_bounds__(256) split_bf16(const float* __restrict__ src,
                                                  int dst_sel, size_t dst_off, int n4) {
    int i = blockIdx.x * 256 + threadIdx.x;
    if (i >= n4) return;
    __nv_bfloat16* hi; __nv_bfloat16* lo;
    if (dst_sel == 0)      { hi = g_Ahi; lo = g_Alo; }
    else if (dst_sel == 1) { hi = g_Bhi; lo = g_Blo; }
    else                   { hi = g_Whi; lo = g_Wlo; }
    hi += dst_off; lo += dst_off;
    uint2 H, L;
    split4(((const float4*)src)[i], H, L);
    ((uint2*)hi)[i] = H;
    ((uint2*)lo)[i] = L;
}

// both raw weights -> g_Shi/Slo (no transpose needed: spectrum(WW^T)=spectrum(W^T W))
__global__ void __launch_bounds__(256) split_W2(const float* __restrict__ Win,
                                                const float* __restrict__ Wout) {
    int g = blockIdx.y;
    int i = blockIdx.x * 256 + threadIdx.x;          // < 262144
    const float* src = g ? Wout : Win;
    uint2 H, L;
    split4(((const float4*)src)[i], H, L);
    ((uint2*)(g_Shi + (size_t)g * 1048576))[i] = H;
    ((uint2*)(g_Slo + (size_t)g * 1048576))[i] = L;
}

// g_Gk[g] * (1024/trace[g][step]) -> g_Shi/Slo[g]
__global__ void __launch_bounds__(256) split_scaled(int step) {
    int g = blockIdx.y;
    int i = blockIdx.x * 256 + threadIdx.x;
    float s = 1024.0f / g_trace[g * 16 + step];
    float4 v = ((const float4*)(g_Gk + (size_t)g * 1048576))[i];
    v.x *= s; v.y *= s; v.z *= s; v.w *= s;
    uint2 H, L;
    split4(v, H, L);
    ((uint2*)(g_Shi + (size_t)g * 1048576))[i] = H;
    ((uint2*)(g_Slo + (size_t)g * 1048576))[i] = L;
}

__global__ void __launch_bounds__(256) copy_G0() {
    int g = blockIdx.y;
    int i = blockIdx.x * 256 + threadIdx.x;
    ((float4*)(g_G0 + (size_t)g * 1048576))[i] = ((const float4*)(g_Gk + (size_t)g * 1048576))[i];
}

__global__ void __launch_bounds__(1024) init_spec() {
    int t = threadIdx.x;
    float v = 0.5f + __sinf((float)t * 0.7311f);
    g_pv[t] = v;
    g_pv[1024 + t] = v;
    if (t < 32) g_trace[t] = 0.f;
    if (t < 2) g_acc[t] = 0.f;
}

// ---------------------------------------------------------------------------
// Small matvec helpers (batched over g)
// ---------------------------------------------------------------------------
__global__ void __launch_bounds__(256) mv_kernel() {
    int g = blockIdx.y;
    const float* G = g_Gk + (size_t)g * 1048576;
    const float4* V4 = (const float4*)(g_pv + g * 1024);
    int w = threadIdx.x >> 5, lane = threadIdx.x & 31;
    #pragma unroll
    for (int rr = 0; rr < 2; rr++) {
        int r = blockIdx.x * 16 + w * 2 + rr;
        const float4* Gr = (const float4*)(G + (size_t)r * 1024);
        float s = 0.f;
        #pragma unroll 4
        for (int j = lane; j < 256; j += 32) {
            float4 a = Gr[j], x = V4[j];
            s += a.x * x.x + a.y * x.y + a.z * x.z + a.w * x.w;
        }
        #pragma unroll
        for (int o = 16; o > 0; o >>= 1) s += __shfl_xor_sync(0xffffffffu, s, o);
        if (lane == 0) g_pw[g * 1024 + r] = s;
    }
}

__global__ void __launch_bounds__(1024) vnorm_kernel() {
    __shared__ float sp[32];
    int g = blockIdx.x;
    int t = threadIdx.x, lane = t & 31, w = t >> 5;
    float v = g_pw[g * 1024 + t];
    float p = v * v;
    #pragma unroll
    for (int o = 16; o > 0; o >>= 1) p += __shfl_xor_sync(0xffffffffu, p, o);
    if (lane == 0) sp[w] = p;
    __syncthreads();
    if (w == 0) {
        float q = sp[lane];
        #pragma unroll
        for (int o = 16; o > 0; o >>= 1) q += __shfl_xor_sync(0xffffffffu, q, o);
        if (lane == 0) sp[0] = rsqrtf(q);
    }
    __syncthreads();
    g_pv[g * 1024 + t] = v * sp[0];
}

// Rayleigh quotient v^T G0 v  (v unit) -> g_acc[g]
__global__ void __launch_bounds__(256) rq_kernel() {
    int g = blockIdx.y;
    const float* G0 = g_G0 + (size_t)g * 1048576;
    const float4* V4 = (const float4*)(g_pv + g * 1024);
    int w = threadIdx.x >> 5, lane = threadIdx.x & 31;
    float part = 0.f;
    #pragma unroll
    for (int rr = 0; rr < 2; rr++) {
        int r = blockIdx.x * 16 + w * 2 + rr;
        const float4* Gr = (const float4*)(G0 + (size_t)r * 1024);
        float s = 0.f;
        #pragma unroll 4
        for (int j = lane; j < 256; j += 32) {
            float4 a = Gr[j], x = V4[j];
            s += a.x * x.x + a.y * x.y + a.z * x.z + a.w * x.w;
        }
        #pragma unroll
        for (int o = 16; o > 0; o >>= 1) s += __shfl_xor_sync(0xffffffffu, s, o);
        if (lane == 0) part += s * g_pv[g * 1024 + r];
    }
    if (lane == 0) atomicAdd(&g_acc[g], part);
}

__global__ void fin_sigma() {
    if (threadIdx.x < 2)
        g_sigma[threadIdx.x] = fmaxf(1.0f, sqrtf(fmaxf(g_acc[threadIdx.x], 0.f)));
}

// ---------------------------------------------------------------------------
// HMMA GEMM (NT), bf16 hi/lo 3-term split, 3-stage cp.async pipeline.
// TBM x 128 x 64 tiles, 8 warps (4m x 2n).
// MODE 0: A=g_Ahi/lo, B=g_Bhi/lo, C=g_RAW (ldc 4096), +bias for col<3072
// MODE 1: A=g_Yhi/lo, B=g_Whi/lo, C=out (ldc 1024), * 1/(s0*s1)
// MODE 2: A=B=g_Shi/lo[z],  C=g_Gk[z], trace -> g_trace[z*16+step]
// ---------------------------------------------------------------------------
template <int TBM>
__device__ __forceinline__ void load_tiles(
    uint32_t base,
    const __nv_bfloat16* __restrict__ Ah, const __nv_bfloat16* __restrict__ Al,
    const __nv_bfloat16* __restrict__ Bh, const __nv_bfloat16* __restrict__ Bl,
    int tid)
{
    constexpr uint32_t AB = TBM * 128;
    uint32_t sAhi = base, sAlo = base + AB, sBhi = base + 2 * AB, sBlo = base + 2 * AB + 16384;
    #pragma unroll
    for (int it = 0; it < TBM / 32; it++) {        // A: TBM rows x 8 x 16B
        int idx = tid + it * 256;
        int r = idx >> 3, c8 = idx & 7;
        uint32_t sw = (uint32_t)r * 128 + (((uint32_t)c8 * 16) ^ (((uint32_t)r & 7) << 4));
        CP_ASYNC16(sAhi + sw, (const char*)(Ah + (size_t)r * KDIM) + c8 * 16);
        CP_ASYNC16(sAlo + sw, (const char*)(Al + (size_t)r * KDIM) + c8 * 16);
    }
    #pragma unroll
    for (int it = 0; it < 4; it++) {               // B: 128 rows x 8 x 16B
        int idx = tid + it * 256;
        int r = idx >> 3, c8 = idx & 7;
        uint32_t sw = (uint32_t)r * 128 + (((uint32_t)c8 * 16) ^ (((uint32_t)r & 7) << 4));
        CP_ASYNC16(sBhi + sw, (const char*)(Bh + (size_t)r * KDIM) + c8 * 16);
        CP_ASYNC16(sBlo + sw, (const char*)(Bl + (size_t)r * KDIM) + c8 * 16);
    }
}

template <int MODE, int TBM>
__global__ void __launch_bounds__(256, 1) mma_gemm(
    const float* __restrict__ bias, float* __restrict__ Cout, int step)
{
    constexpr int MT = TBM / 64;                   // m16 tiles per warp
    constexpr uint32_t AB = TBM * 128;
    constexpr uint32_t STAGE = 2 * AB + 32768;
    extern __shared__ char smem[];
    uint32_t sb = smem_u32(smem);
    int tid = threadIdx.x, wid = tid >> 5, lane = tid & 31;
    int m0 = blockIdx.y * TBM;
    int n0 = blockIdx.x * GBN;
    int wm = wid >> 1, wn = wid & 1;
    int m_off = wm * (TBM / 4), n_off = wn * 64;

    size_t goff = (MODE == 2) ? (size_t)blockIdx.z * 1048576 : 0;
    const __nv_bfloat16* Ah = (MODE == 0 ? g_Ahi : MODE == 1 ? g_Yhi : g_Shi) + goff + (size_t)m0 * KDIM;
    const __nv_bfloat16* Al = (MODE == 0 ? g_Alo : MODE == 1 ? g_Ylo : g_Slo) + goff + (size_t)m0 * KDIM;
    const __nv_bfloat16* Bh = (MODE == 0 ? g_Bhi : MODE == 1 ? g_Whi : g_Shi) + goff + (size_t)n0 * KDIM;
    const __nv_bfloat16* Bl = (MODE == 0 ? g_Blo : MODE == 1 ? g_Wlo : g_Slo) + goff + (size_t)n0 * KDIM;
    float* C = (MODE == 0) ? g_RAW : (MODE == 1) ? Cout : (g_Gk + goff);
    const int ldc = (MODE == 0) ? NRAW : NN;

    float acc[MT][8][4];
    #pragma unroll
    for (int mt = 0; mt < MT; mt++)
        #pragma unroll
        for (int n = 0; n < 8; n++)
            #pragma unroll
            for (int j = 0; j < 4; j++) acc[mt][n][j] = 0.f;

    int lrow = lane & 15;
    uint32_t lcol = ((uint32_t)(lane >> 4)) << 4;

    // prologue: stages 0, 1
    load_tiles<TBM>(sb,         Ah,      Al,      Bh,      Bl,      tid); CP_COMMIT();
    load_tiles<TBM>(sb + STAGE, Ah + 64, Al + 64, Bh + 64, Bl + 64, tid); CP_COMMIT();

    for (int ch = 0; ch < KCH; ch++) {
        if (ch == KCH - 1) { CP_WAIT0(); } else { CP_WAIT1(); }
        __syncthreads();
        // prefetch ch+2 BEFORE compute (2-chunk overlap); buffer (ch+2)%3 freed in iter ch-1
        if (ch + 2 < KCH) {
            int k0 = (ch + 2) * GBK;
            load_tiles<TBM>(sb + ((ch + 2) % 3) * STAGE, Ah + k0, Al + k0, Bh + k0, Bl + k0, tid);
            CP_COMMIT();
        }
        uint32_t base = sb + (ch % 3) * STAGE;
        #pragma unroll
        for (int ks = 0; ks < 4; ks++) {
            uint32_t cb = (uint32_t)ks * 32 + lcol;
            uint32_t ahi[MT][4], alo[MT][4];
            #pragma unroll
            for (int mt = 0; mt < MT; mt++) {
                int row = m_off + mt * 16 + lrow;
                uint32_t ad = base + (uint32_t)row * 128 + (cb ^ (((uint32_t)row & 7) << 4));
                LDMATRIX_X4(ahi[mt][0], ahi[mt][1], ahi[mt][2], ahi[mt][3], ad);
                LDMATRIX_X4(alo[mt][0], alo[mt][1], alo[mt][2], alo[mt][3], ad + AB);
            }
            uint32_t bhi[8][2], blo[8][2];
            #pragma unroll
            for (int nt = 0; nt < 4; nt++) {
                int row = n_off + nt * 16 + lrow;
                uint32_t bd = base + 2 * AB + (uint32_t)row * 128 + (cb ^ (((uint32_t)row & 7) << 4));
                uint32_t r0, r1, r2, r3;
                LDMATRIX_X4(r0, r1, r2, r3, bd);
                bhi[nt * 2][0] = r0; bhi[nt * 2][1] = r2;
                bhi[nt * 2 + 1][0] = r1; bhi[nt * 2 + 1][1] = r3;
                LDMATRIX_X4(r0, r1, r2, r3, bd + 16384);
                blo[nt * 2][0] = r0; blo[nt * 2][1] = r2;
                blo[nt * 2 + 1][0] = r1; blo[nt * 2 + 1][1] = r3;
            }
            #pragma unroll
            for (int mt = 0; mt < MT; mt++)
                #pragma unroll
                for (int n = 0; n < 8; n++) {
                    MMA_BF16(acc[mt][n], ahi[mt], bhi[n]);
                    MMA_BF16(acc[mt][n], ahi[mt], blo[n]);
                    MMA_BF16(acc[mt][n], alo[mt], bhi[n]);
                }
        }
    }

    float scale = 1.0f;
    if (MODE == 1) scale = 1.0f / (g_sigma[0] * g_sigma[1]);
    int gid = lane >> 2, tig = lane & 3;
    float tp = 0.f;
    bool diag = (MODE == 2) && (m0 < n0 + GBN) && (n0 < m0 + TBM);

    #pragma unroll
    for (int mt = 0; mt < MT; mt++) {
        #pragma unroll
        for (int n = 0; n < 8; n++) {
            int col = n0 + n_off + n * 8 + tig * 2;
            int r0 = m0 + m_off + mt * 16 + gid;
            float2 v0 = make_float2(acc[mt][n][0], acc[mt][n][1]);
            float2 v1 = make_float2(acc[mt][n][2], acc[mt][n][3]);
            if (MODE == 0) {
                if (col < 3072) {
                    float b0 = __ldg(&bias[col]), b1 = __ldg(&bias[col + 1]);
                    v0.x += b0; v0.y += b1; v1.x += b0; v1.y += b1;
                }
            } else if (MODE == 1) {
                v0.x *= scale; v0.y *= scale; v1.x *= scale; v1.y *= scale;
            } else if (diag) {
                if (r0 == col)         tp += v0.x;
                if (r0 == col + 1)     tp += v0.y;
                if (r0 + 8 == col)     tp += v1.x;
                if (r0 + 8 == col + 1) tp += v1.y;
            }
            *(float2*)(C + (size_t)r0 * ldc + col) = v0;
            *(float2*)(C + (size_t)(r0 + 8) * ldc + col) = v1;
        }
    }
    if (MODE == 2 && diag && tp != 0.f)
        atomicAdd(&g_trace[blockIdx.z * 16 + step], tp);
}

// ---------------------------------------------------------------------------
// Fused elementwise + scan pass1
// ---------------------------------------------------------------------------
__device__ __forceinline__ float softplus_f(float x) {
    return fmaxf(x, 0.f) + log1pf(expf(-fabsf(x)));
}
__device__ __forceinline__ float tanh_fast(float x) {
    const float L2E2 = 2.8853900817779268f;
    float ax = fabsf(x);
    float e = exp2f(ax * L2E2);
    float r = 1.0f - 2.0f / (e + 1.0f);
    return copysignf(r, x);
}

__global__ void __launch_bounds__(128) ew_scan1(
    const float* __restrict__ alpha_log, const float* __restrict__ delta_bias,
    const float* __restrict__ log_gamma)
{
    const float L2E = 1.4426950408889634f;
    int blk = blockIdx.x;
    int ib = blk & 7;
    int chunk = (blk >> 3) & 31;
    int b = blk >> 8;
    int i = ib * 128 + threadIdx.x;
    size_t base = ((size_t)(b * TT + chunk * LCHUNK)) * NRAW + i;

    float alpha = softplus_f(alpha_log[i]);
    float db    = delta_bias[i];
    float gamma = expf(log_gamma[0]);

    float A = 1.f, Bc = 0.f;
    for (int t = 0; t < LCHUNK; t++) {
        size_t o = base + (size_t)t * NRAW;
        float dr  = g_RAW[o];
        float brw = g_RAW[o + 1024];
        float crw = g_RAW[o + 2048];
        float gg  = g_RAW[o + 3072];

        float s  = dr + db;
        float t1 = exp2f(s * L2E);
        float Lg = log2f(1.0f + t1);
        float a  = exp2f(-alpha * Lg);
        a = fminf(a, 1.0f - 1e-4f);

        float bv = tanh_fast(brw);
        float cv = tanh_fast(crw);

        float p  = a * a + cv * cv;
        float r2 = bv * bv;
        float q  = a * bv;
        float d1 = p - r2;
        float disc = fmaf(d1, d1, 4.0f * q * q) + 1e-12f;
        float sq   = disc * rsqrtf(disc);
        float lam  = 0.5f * (p + r2 + sq) + 1e-12f;
        float inv  = rsqrtf(fmaxf(lam, 1.0f));

        a  *= inv;
        bv *= inv;
        cv *= inv;

        float bu = bv * gamma * gg;
        g_RAW[o]        = a;
        g_RAW[o + 1024] = bu;
        g_RAW[o + 2048] = cv;

        Bc = fmaf(a, Bc, bu);
        A *= a;
    }
    int ai = (b * NCHUNK + chunk) * NN + i;
    g_AggA[ai] = A;
    g_AggB[ai] = Bc;
}

__global__ void __launch_bounds__(1024) scan_pass2() {
    int ch = blockIdx.x * 1024 + threadIdx.x;
    int b = ch >> 10;
    int i = ch & 1023;
    float carry = 0.f;
    for (int c = 0; c < NCHUNK; c++) {
        int ai = (b * NCHUNK + c) * NN + i;
        g_Z0[ai] = carry;
        carry = fmaf(g_AggA[ai], carry, g_AggB[ai]);
    }
}

__global__ void __launch_bounds__(128) scan_pass3() {
    int blk = blockIdx.x;
    int ib = blk & 7;
    int chunk = (blk >> 3) & 31;
    int b = blk >> 8;
    int i = ib * 128 + threadIdx.x;
    int bt0 = b * TT + chunk * LCHUNK;
    size_t base = (size_t)bt0 * NRAW + i;
    float z = g_Z0[(b * NCHUNK + chunk) * NN + i];
    for (int t = 0; t < LCHUNK; t++) {
        size_t o = base + (size_t)t * NRAW;
        float a  = g_RAW[o];
        float bu = g_RAW[o + 1024];
        float c  = g_RAW[o + 2048];
        float y  = c * z;
        size_t yo = (size_t)(bt0 + t) * NN + i;
        __nv_bfloat16 h = __float2bfloat16(y);
        g_Yhi[yo] = h;
        g_Ylo[yo] = __float2bfloat16(y - __bfloat162float(h));
        z = fmaf(a, z, bu);
    }
}

// ---------------------------------------------------------------------------
// Launch
// ---------------------------------------------------------------------------
extern "C" void kernel_launch(void* const* d_in, const int* in_sizes, int n_in,
                              void* d_out, int out_size)
{
    (void)in_sizes; (void)n_in; (void)out_size;
    const float* u          = (const float*)d_in[0];
    const float* W_in       = (const float*)d_in[1];
    const float* W_out      = (const float*)d_in[2];
    const float* Wp         = (const float*)d_in[3];
    const float* bp         = (const float*)d_in[4];
    const float* alpha_log  = (const float*)d_in[5];
    const float* delta_bias = (const float*)d_in[6];
    const float* log_gamma  = (const float*)d_in[7];
    float* out = (float*)d_out;

    cudaFuncSetAttribute((const void*)mma_gemm<0, 128>, cudaFuncAttributeMaxDynamicSharedMemorySize, SM128);
    cudaFuncSetAttribute((const void*)mma_gemm<1, 128>, cudaFuncAttributeMaxDynamicSharedMemorySize, SM128);
    cudaFuncSetAttribute((const void*)mma_gemm<2, 64>,  cudaFuncAttributeMaxDynamicSharedMemorySize, SM64);

    // ---- spectral norms: batched repeated squaring + Rayleigh quotient ----
    split_W2<<<dim3(1024, 2), 256>>>(W_in, W_out);
    init_spec<<<1, 1024>>>();
    mma_gemm<2, 64><<<dim3(8, 16, 2), 256, SM64>>>(nullptr, nullptr, 0);   // G0 = W W^T
    copy_G0<<<dim3(1024, 2), 256>>>();
    for (int k = 1; k <= NSQ; k++) {
        split_scaled<<<dim3(1024, 2), 256>>>(k - 1);
        mma_gemm<2, 64><<<dim3(8, 16, 2), 256, SM64>>>(nullptr, nullptr, k);
    }
    for (int r = 0; r < NMV; r++) {
        mv_kernel<<<dim3(64, 2), 256>>>();
        vnorm_kernel<<<2, 1024>>>();
    }
    rq_kernel<<<dim3(64, 2), 256>>>();
    fin_sigma<<<1, 32>>>();

    // ---- main path ----
    split_bf16<<<(BT * KDIM / 4 + 255) / 256, 256>>>(u, 0, 0, BT * KDIM / 4);
    split_bf16<<<(3072 * KDIM / 4 + 255) / 256, 256>>>(Wp, 1, 0, 3072 * KDIM / 4);
    split_bf16<<<(NN * KDIM / 4 + 255) / 256, 256>>>(W_in, 1, (size_t)3072 * KDIM, NN * KDIM / 4);
    split_bf16<<<(NN * KDIM / 4 + 255) / 256, 256>>>(W_out, 2, 0, NN * KDIM / 4);

    // GEMM1: raw = u @ [Wp ; W_in]^T  (+bp on Wp cols)
    mma_gemm<0, 128><<<dim3(NRAW / GBN, BT / 128), 256, SM128>>>(bp, nullptr, 0);

    ew_scan1<<<BB * NCHUNK * 8, 128>>>(alpha_log, delta_bias, log_gamma);
    scan_pass2<<<4, 1024>>>();
    scan_pass3<<<BB * NCHUNK * 8, 128>>>();

    // GEMM2: y = y_hat @ W_out^T * 1/(s0*s1)
    mma_gemm<1, 128><<<dim3(NN / GBN, BT / 128), 256, SM128>>>(nullptr, out, 0);
}

// round 6
// speedup vs baseline: 6.6043x; 1.3186x over previous
#include <cuda_runtime.h>
#include <cuda_fp16.h>
#include <math.h>
#include <stdint.h>

// Problem constants
#define BB   4
#define TT   4096
#define NN   1024
#define BT   16384
#define NRAW 4096
#define NCHUNK 32
#define LCHUNK 128

// GEMM tiling (HMMA mma.sync; tcgen05 unavailable: harness targets sm_103 w/o 'a')
#define GBN 128
#define GBK 64
#define KDIM 1024
#define KCH  16                          // KDIM/GBK

#define NSQ 8                            // squarings -> G^(2^NSQ)
#define NMV 4                            // chained matvecs

// stage = A(TBM*128B) + Bhi(16K) + Blo(16K); 3 stages
#define SM128 147456                     // 3 * (16384 + 32768)
#define SM64  122880                     // 3 * ( 8192 + 32768)

// ---------------------------------------------------------------------------
// Device scratch
// ---------------------------------------------------------------------------
__device__ __align__(128) float g_RAW[(size_t)BT * NRAW];
__device__ __align__(128) __half g_Ahi[(size_t)BT * KDIM];            // u (hi only)
__device__ __align__(128) __half g_Bhi[(size_t)NRAW * KDIM];          // [Wp(3072) ; W_in(1024)]
__device__ __align__(128) __half g_Blo[(size_t)NRAW * KDIM];
__device__ __align__(128) __half g_Whi[(size_t)NN * KDIM];            // W_out
__device__ __align__(128) __half g_Wlo[(size_t)NN * KDIM];
__device__ __align__(128) __half g_Yhi[(size_t)BT * NN];              // y_hat (hi only)
__device__ float g_AggA[BB * NCHUNK * NN];
__device__ float g_AggB[BB * NCHUNK * NN];
__device__ float g_Z0[BB * NCHUNK * NN];

// spectral-norm machinery (batched over both weights, index g in {0,1})
__device__ __align__(128) __half g_Shi[2 * 1024 * 1024];
__device__ __align__(128) __half g_Slo[2 * 1024 * 1024];
__device__ __align__(128) float g_Gk[2 * 1024 * 1024];
__device__ __align__(128) float g_G0[2 * 1024 * 1024];
__device__ float g_pv[2 * 1024];
__device__ float g_pw[2 * 1024];
__device__ float g_trace[32];            // [g*16 + step]
__device__ float g_acc[2];
__device__ float g_sigma[2];

// ---------------------------------------------------------------------------
// PTX helpers
// ---------------------------------------------------------------------------
__device__ __forceinline__ uint32_t smem_u32(const void* p) {
    uint32_t a;
    asm("{ .reg .u64 t; cvta.to.shared.u64 t, %1; cvt.u32.u64 %0, t; }" : "=r"(a) : "l"(p));
    return a;
}

#define CP_ASYNC16(dst, src) \
    asm volatile("cp.async.cg.shared.global [%0], [%1], 16;" :: "r"(dst), "l"(src))
#define CP_COMMIT() asm volatile("cp.async.commit_group;" ::: "memory")
#define CP_WAIT1()  asm volatile("cp.async.wait_group 1;" ::: "memory")
#define CP_WAIT0()  asm volatile("cp.async.wait_group 0;" ::: "memory")

#define LDMATRIX_X4(r0, r1, r2, r3, addr) \
    asm volatile("ldmatrix.sync.aligned.m8n8.x4.shared.b16 {%0,%1,%2,%3}, [%4];" \
                 : "=r"(r0), "=r"(r1), "=r"(r2), "=r"(r3) : "r"(addr))

#define MMA_FP16(d, a, b) \
    asm volatile("mma.sync.aligned.m16n8k16.row.col.f32.f16.f16.f32 " \
        "{%0,%1,%2,%3}, {%4,%5,%6,%7}, {%8,%9}, {%0,%1,%2,%3};" \
        : "+f"((d)[0]), "+f"((d)[1]), "+f"((d)[2]), "+f"((d)[3]) \
        : "r"((a)[0]), "r"((a)[1]), "r"((a)[2]), "r"((a)[3]), "r"((b)[0]), "r"((b)[1]))

// ---------------------------------------------------------------------------
// fp16 hi/lo split helpers
// ---------------------------------------------------------------------------
__device__ __forceinline__ void split4h(const float4 v, uint2& H, uint2& L) {
    union { __half b[4]; uint2 u; } h, l;
    float x[4] = {v.x, v.y, v.z, v.w};
    #pragma unroll
    for (int j = 0; j < 4; j++) {
        __half hb = __float2half_rn(x[j]);
        h.b[j] = hb;
        l.b[j] = __float2half_rn(x[j] - __half2float(hb));
    }
    H = h.u; L = l.u;
}
__device__ __forceinline__ uint2 hi4h(const float4 v) {
    union { __half b[4]; uint2 u; } h;
    h.b[0] = __float2half_rn(v.x); h.b[1] = __float2half_rn(v.y);
    h.b[2] = __float2half_rn(v.z); h.b[3] = __float2half_rn(v.w);
    return h.u;
}

// dst_sel: 0 -> A(u, hi only), 1 -> B fused (hi+lo), 2 -> W_out (hi+lo)
__global__ void __launch_bounds__(256) split_half(const float* __restrict__ src,
                                                  int dst_sel, size_t dst_off, int n4) {
    int i = blockIdx.x * 256 + threadIdx.x;
    if (i >= n4) return;
    float4 v = ((const float4*)src)[i];
    if (dst_sel == 0) {
        ((uint2*)g_Ahi)[i] = hi4h(v);
        return;
    }
    __half* hi = (dst_sel == 1) ? g_Bhi : g_Whi;
    __half* lo = (dst_sel == 1) ? g_Blo : g_Wlo;
    hi += dst_off; lo += dst_off;
    uint2 H, L;
    split4h(v, H, L);
    ((uint2*)hi)[i] = H;
    ((uint2*)lo)[i] = L;
}

// both raw weights -> g_Shi/Slo (spectrum(WW^T)=spectrum(W^T W) -> no transpose)
__global__ void __launch_bounds__(256) split_W2(const float* __restrict__ Win,
                                                const float* __restrict__ Wout) {
    int g = blockIdx.y;
    int i = blockIdx.x * 256 + threadIdx.x;          // < 262144
    const float* src = g ? Wout : Win;
    uint2 H, L;
    split4h(((const float4*)src)[i], H, L);
    ((uint2*)(g_Shi + (size_t)g * 1048576))[i] = H;
    ((uint2*)(g_Slo + (size_t)g * 1048576))[i] = L;
}

// g_Gk[g] * (1024/trace[g][step]) -> g_Shi/Slo[g]
__global__ void __launch_bounds__(256) split_scaled(int step) {
    int g = blockIdx.y;
    int i = blockIdx.x * 256 + threadIdx.x;
    float s = 1024.0f / g_trace[g * 16 + step];
    float4 v = ((const float4*)(g_Gk + (size_t)g * 1048576))[i];
    v.x *= s; v.y *= s; v.z *= s; v.w *= s;
    uint2 H, L;
    split4h(v, H, L);
    ((uint2*)(g_Shi + (size_t)g * 1048576))[i] = H;
    ((uint2*)(g_Slo + (size_t)g * 1048576))[i] = L;
}

__global__ void __launch_bounds__(1024) init_spec() {
    int t = threadIdx.x;
    float v = 0.5f + __sinf((float)t * 0.7311f);
    g_pv[t] = v;
    g_pv[1024 + t] = v;
    if (t < 32) g_trace[t] = 0.f;
    if (t < 2) g_acc[t] = 0.f;
}

// ---------------------------------------------------------------------------
// Small matvec helpers (batched over g)
// ---------------------------------------------------------------------------
__global__ void __launch_bounds__(256) mv_kernel() {
    int g = blockIdx.y;
    const float* G = g_Gk + (size_t)g * 1048576;
    const float4* V4 = (const float4*)(g_pv + g * 1024);
    int w = threadIdx.x >> 5, lane = threadIdx.x & 31;
    #pragma unroll
    for (int rr = 0; rr < 2; rr++) {
        int r = blockIdx.x * 16 + w * 2 + rr;
        const float4* Gr = (const float4*)(G + (size_t)r * 1024);
        float s = 0.f;
        #pragma unroll 4
        for (int j = lane; j < 256; j += 32) {
            float4 a = Gr[j], x = V4[j];
            s += a.x * x.x + a.y * x.y + a.z * x.z + a.w * x.w;
        }
        #pragma unroll
        for (int o = 16; o > 0; o >>= 1) s += __shfl_xor_sync(0xffffffffu, s, o);
        if (lane == 0) g_pw[g * 1024 + r] = s;
    }
}

__global__ void __launch_bounds__(1024) vnorm_kernel() {
    __shared__ float sp[32];
    int g = blockIdx.x;
    int t = threadIdx.x, lane = t & 31, w = t >> 5;
    float v = g_pw[g * 1024 + t];
    float p = v * v;
    #pragma unroll
    for (int o = 16; o > 0; o >>= 1) p += __shfl_xor_sync(0xffffffffu, p, o);
    if (lane == 0) sp[w] = p;
    __syncthreads();
    if (w == 0) {
        float q = sp[lane];
        #pragma unroll
        for (int o = 16; o > 0; o >>= 1) q += __shfl_xor_sync(0xffffffffu, q, o);
        if (lane == 0) sp[0] = rsqrtf(q);
    }
    __syncthreads();
    g_pv[g * 1024 + t] = v * sp[0];
}

// Rayleigh quotient v^T G0 v  (v unit) -> g_acc[g]
__global__ void __launch_bounds__(256) rq_kernel() {
    int g = blockIdx.y;
    const float* G0 = g_G0 + (size_t)g * 1048576;
    const float4* V4 = (const float4*)(g_pv + g * 1024);
    int w = threadIdx.x >> 5, lane = threadIdx.x & 31;
    float part = 0.f;
    #pragma unroll
    for (int rr = 0; rr < 2; rr++) {
        int r = blockIdx.x * 16 + w * 2 + rr;
        const float4* Gr = (const float4*)(G0 + (size_t)r * 1024);
        float s = 0.f;
        #pragma unroll 4
        for (int j = lane; j < 256; j += 32) {
            float4 a = Gr[j], x = V4[j];
            s += a.x * x.x + a.y * x.y + a.z * x.z + a.w * x.w;
        }
        #pragma unroll
        for (int o = 16; o > 0; o >>= 1) s += __shfl_xor_sync(0xffffffffu, s, o);
        if (lane == 0) part += s * g_pv[g * 1024 + r];
    }
    if (lane == 0) atomicAdd(&g_acc[g], part);
}

__global__ void fin_sigma() {
    if (threadIdx.x < 2)
        g_sigma[threadIdx.x] = fmaxf(1.0f, sqrtf(fmaxf(g_acc[threadIdx.x], 0.f)));
}

// ---------------------------------------------------------------------------
// HMMA GEMM (NT), fp16 2-term split: C = Ahi*Bhi + Ahi*Blo  (= A*B - epsA*B)
// TBM x 128 x 64 tiles, 8 warps (4m x 2n), 3-stage cp.async pipeline.
// MODE 0: A=g_Ahi,  B=g_Bhi/lo, C=g_RAW (ldc 4096), +bias for col<3072
// MODE 1: A=g_Yhi,  B=g_Whi/lo, C=out (ldc 1024), * 1/(s0*s1)
// MODE 2: A=g_Shi[z], B=g_Shi/lo[z], C=g_Gk[z] (+g_G0 when step==0),
//         trace -> g_trace[z*16+step]
// ---------------------------------------------------------------------------
template <int TBM>
__device__ __forceinline__ void load_tiles(
    uint32_t base,
    const __half* __restrict__ Ah,
    const __half* __restrict__ Bh, const __half* __restrict__ Bl,
    int tid)
{
    constexpr uint32_t AB = TBM * 128;
    uint32_t sA = base, sBhi = base + AB, sBlo = base + AB + 16384;
    #pragma unroll
    for (int it = 0; it < TBM / 32; it++) {        // A: TBM rows x 8 x 16B
        int idx = tid + it * 256;
        int r = idx >> 3, c8 = idx & 7;
        uint32_t sw = (uint32_t)r * 128 + (((uint32_t)c8 * 16) ^ (((uint32_t)r & 7) << 4));
        CP_ASYNC16(sA + sw, (const char*)(Ah + (size_t)r * KDIM) + c8 * 16);
    }
    #pragma unroll
    for (int it = 0; it < 4; it++) {               // B: 128 rows x 8 x 16B (hi+lo)
        int idx = tid + it * 256;
        int r = idx >> 3, c8 = idx & 7;
        uint32_t sw = (uint32_t)r * 128 + (((uint32_t)c8 * 16) ^ (((uint32_t)r & 7) << 4));
        CP_ASYNC16(sBhi + sw, (const char*)(Bh + (size_t)r * KDIM) + c8 * 16);
        CP_ASYNC16(sBlo + sw, (const char*)(Bl + (size_t)r * KDIM) + c8 * 16);
    }
}

template <int MODE, int TBM>
__global__ void __launch_bounds__(256, 1) mma_gemm(
    const float* __restrict__ bias, float* __restrict__ Cout, int step)
{
    constexpr int MT = TBM / 64;                   // m16 tiles per warp
    constexpr uint32_t AB = TBM * 128;
    constexpr uint32_t STAGE = AB + 32768;
    extern __shared__ char smem[];
    uint32_t sb = smem_u32(smem);
    int tid = threadIdx.x, wid = tid >> 5, lane = tid & 31;
    int m0 = blockIdx.y * TBM;
    int n0 = blockIdx.x * GBN;
    int wm = wid >> 1, wn = wid & 1;
    int m_off = wm * (TBM / 4), n_off = wn * 64;

    size_t goff = (MODE == 2) ? (size_t)blockIdx.z * 1048576 : 0;
    const __half* Ah = (MODE == 0 ? g_Ahi : MODE == 1 ? g_Yhi : g_Shi) + goff + (size_t)m0 * KDIM;
    const __half* Bh = (MODE == 0 ? g_Bhi : MODE == 1 ? g_Whi : g_Shi) + goff + (size_t)n0 * KDIM;
    const __half* Bl = (MODE == 0 ? g_Blo : MODE == 1 ? g_Wlo : g_Slo) + goff + (size_t)n0 * KDIM;
    float* C = (MODE == 0) ? g_RAW : (MODE == 1) ? Cout : (g_Gk + goff);
    const int ldc = (MODE == 0) ? NRAW : NN;

    float acc[MT][8][4];
    #pragma unroll
    for (int mt = 0; mt < MT; mt++)
        #pragma unroll
        for (int n = 0; n < 8; n++)
            #pragma unroll
            for (int j = 0; j < 4; j++) acc[mt][n][j] = 0.f;

    int lrow = lane & 15;
    uint32_t lcol = ((uint32_t)(lane >> 4)) << 4;

    // prologue: stages 0, 1
    load_tiles<TBM>(sb,         Ah,      Bh,      Bl,      tid); CP_COMMIT();
    load_tiles<TBM>(sb + STAGE, Ah + 64, Bh + 64, Bl + 64, tid); CP_COMMIT();

    for (int ch = 0; ch < KCH; ch++) {
        if (ch == KCH - 1) { CP_WAIT0(); } else { CP_WAIT1(); }
        __syncthreads();
        // prefetch ch+2 BEFORE compute; buffer (ch+2)%3 was freed in iter ch-1
        if (ch + 2 < KCH) {
            int k0 = (ch + 2) * GBK;
            load_tiles<TBM>(sb + ((ch + 2) % 3) * STAGE, Ah + k0, Bh + k0, Bl + k0, tid);
            CP_COMMIT();
        }
        uint32_t base = sb + (ch % 3) * STAGE;
        #pragma unroll
        for (int ks = 0; ks < 4; ks++) {
            uint32_t cb = (uint32_t)ks * 32 + lcol;
            uint32_t ahi[MT][4];
            #pragma unroll
            for (int mt = 0; mt < MT; mt++) {
                int row = m_off + mt * 16 + lrow;
                uint32_t ad = base + (uint32_t)row * 128 + (cb ^ (((uint32_t)row & 7) << 4));
                LDMATRIX_X4(ahi[mt][0], ahi[mt][1], ahi[mt][2], ahi[mt][3], ad);
            }
            uint32_t bhi[8][2], blo[8][2];
            #pragma unroll
            for (int nt = 0; nt < 4; nt++) {
                int row = n_off + nt * 16 + lrow;
                uint32_t bd = base + AB + (uint32_t)row * 128 + (cb ^ (((uint32_t)row & 7) << 4));
                uint32_t r0, r1, r2, r3;
                LDMATRIX_X4(r0, r1, r2, r3, bd);
                bhi[nt * 2][0] = r0; bhi[nt * 2][1] = r2;
                bhi[nt * 2 + 1][0] = r1; bhi[nt * 2 + 1][1] = r3;
                LDMATRIX_X4(r0, r1, r2, r3, bd + 16384);
                blo[nt * 2][0] = r0; blo[nt * 2][1] = r2;
                blo[nt * 2 + 1][0] = r1; blo[nt * 2 + 1][1] = r3;
            }
            #pragma unroll
            for (int mt = 0; mt < MT; mt++)
                #pragma unroll
                for (int n = 0; n < 8; n++) {
                    MMA_FP16(acc[mt][n], ahi[mt], bhi[n]);
                    MMA_FP16(acc[mt][n], ahi[mt], blo[n]);
                }
        }
    }

    float scale = 1.0f;
    if (MODE == 1) scale = 1.0f / (g_sigma[0] * g_sigma[1]);
    int gid = lane >> 2, tig = lane & 3;
    float tp = 0.f;
    bool diag = (MODE == 2) && (m0 < n0 + GBN) && (n0 < m0 + TBM);

    #pragma unroll
    for (int mt = 0; mt < MT; mt++) {
        #pragma unroll
        for (int n = 0; n < 8; n++) {
            int col = n0 + n_off + n * 8 + tig * 2;
            int r0 = m0 + m_off + mt * 16 + gid;
            float2 v0 = make_float2(acc[mt][n][0], acc[mt][n][1]);
            float2 v1 = make_float2(acc[mt][n][2], acc[mt][n][3]);
            if (MODE == 0) {
                if (col < 3072) {
                    float b0 = __ldg(&bias[col]), b1 = __ldg(&bias[col + 1]);
                    v0.x += b0; v0.y += b1; v1.x += b0; v1.y += b1;
                }
            } else if (MODE == 1) {
                v0.x *= scale; v0.y *= scale; v1.x *= scale; v1.y *= scale;
            } else if (diag) {
                if (r0 == col)         tp += v0.x;
                if (r0 == col + 1)     tp += v0.y;
                if (r0 + 8 == col)     tp += v1.x;
                if (r0 + 8 == col + 1) tp += v1.y;
            }
            *(float2*)(C + (size_t)r0 * ldc + col) = v0;
            *(float2*)(C + (size_t)(r0 + 8) * ldc + col) = v1;
            if (MODE == 2 && step == 0) {       // also persist G0 (folds copy_G0)
                float* C0 = g_G0 + goff;
                *(float2*)(C0 + (size_t)r0 * ldc + col) = v0;
                *(float2*)(C0 + (size_t)(r0 + 8) * ldc + col) = v1;
            }
        }
    }
    if (MODE == 2 && diag && tp != 0.f)
        atomicAdd(&g_trace[blockIdx.z * 16 + step], tp);
}

// ---------------------------------------------------------------------------
// Fused elementwise + scan pass1
// ---------------------------------------------------------------------------
__device__ __forceinline__ float softplus_f(float x) {
    return fmaxf(x, 0.f) + log1pf(expf(-fabsf(x)));
}
__device__ __forceinline__ float tanh_fast(float x) {
    const float L2E2 = 2.8853900817779268f;
    float ax = fabsf(x);
    float e = exp2f(ax * L2E2);
    float r = 1.0f - 2.0f / (e + 1.0f);
    return copysignf(r, x);
}

__global__ void __launch_bounds__(128) ew_scan1(
    const float* __restrict__ alpha_log, const float* __restrict__ delta_bias,
    const float* __restrict__ log_gamma)
{
    const float L2E = 1.4426950408889634f;
    int blk = blockIdx.x;
    int ib = blk & 7;
    int chunk = (blk >> 3) & 31;
    int b = blk >> 8;
    int i = ib * 128 + threadIdx.x;
    size_t base = ((size_t)(b * TT + chunk * LCHUNK)) * NRAW + i;

    float alpha = softplus_f(alpha_log[i]);
    float db    = delta_bias[i];
    float gamma = expf(log_gamma[0]);

    float A = 1.f, Bc = 0.f;
    for (int t = 0; t < LCHUNK; t++) {
        size_t o = base + (size_t)t * NRAW;
        float dr  = g_RAW[o];
        float brw = g_RAW[o + 1024];
        float crw = g_RAW[o + 2048];
        float gg  = g_RAW[o + 3072];

        float s  = dr + db;
        float t1 = exp2f(s * L2E);
        float Lg = log2f(1.0f + t1);
        float a  = exp2f(-alpha * Lg);
        a = fminf(a, 1.0f - 1e-4f);

        float bv = tanh_fast(brw);
        float cv = tanh_fast(crw);

        float p  = a * a + cv * cv;
        float r2 = bv * bv;
        float q  = a * bv;
        float d1 = p - r2;
        float disc = fmaf(d1, d1, 4.0f * q * q) + 1e-12f;
        float sq   = disc * rsqrtf(disc);
        float lam  = 0.5f * (p + r2 + sq) + 1e-12f;
        float inv  = rsqrtf(fmaxf(lam, 1.0f));

        a  *= inv;
        bv *= inv;
        cv *= inv;

        float bu = bv * gamma * gg;
        g_RAW[o]        = a;
        g_RAW[o + 1024] = bu;
        g_RAW[o + 2048] = cv;

        Bc = fmaf(a, Bc, bu);
        A *= a;
    }
    int ai = (b * NCHUNK + chunk) * NN + i;
    g_AggA[ai] = A;
    g_AggB[ai] = Bc;
}

__global__ void __launch_bounds__(1024) scan_pass2() {
    int ch = blockIdx.x * 1024 + threadIdx.x;
    int b = ch >> 10;
    int i = ch & 1023;
    float carry = 0.f;
    for (int c = 0; c < NCHUNK; c++) {
        int ai = (b * NCHUNK + c) * NN + i;
        g_Z0[ai] = carry;
        carry = fmaf(g_AggA[ai], carry, g_AggB[ai]);
    }
}

__global__ void __launch_bounds__(128) scan_pass3() {
    int blk = blockIdx.x;
    int ib = blk & 7;
    int chunk = (blk >> 3) & 31;
    int b = blk >> 8;
    int i = ib * 128 + threadIdx.x;
    int bt0 = b * TT + chunk * LCHUNK;
    size_t base = (size_t)bt0 * NRAW + i;
    float z = g_Z0[(b * NCHUNK + chunk) * NN + i];
    for (int t = 0; t < LCHUNK; t++) {
        size_t o = base + (size_t)t * NRAW;
        float a  = g_RAW[o];
        float bu = g_RAW[o + 1024];
        float c  = g_RAW[o + 2048];
        size_t yo = (size_t)(bt0 + t) * NN + i;
        g_Yhi[yo] = __float2half_rn(c * z);
        z = fmaf(a, z, bu);
    }
}

// ---------------------------------------------------------------------------
// Launch
// ---------------------------------------------------------------------------
extern "C" void kernel_launch(void* const* d_in, const int* in_sizes, int n_in,
                              void* d_out, int out_size)
{
    (void)in_sizes; (void)n_in; (void)out_size;
    const float* u          = (const float*)d_in[0];
    const float* W_in       = (const float*)d_in[1];
    const float* W_out      = (const float*)d_in[2];
    const float* Wp         = (const float*)d_in[3];
    const float* bp         = (const float*)d_in[4];
    const float* alpha_log  = (const float*)d_in[5];
    const float* delta_bias = (const float*)d_in[6];
    const float* log_gamma  = (const float*)d_in[7];
    float* out = (float*)d_out;

    cudaFuncSetAttribute((const void*)mma_gemm<0, 128>, cudaFuncAttributeMaxDynamicSharedMemorySize, SM128);
    cudaFuncSetAttribute((const void*)mma_gemm<1, 128>, cudaFuncAttributeMaxDynamicSharedMemorySize, SM128);
    cudaFuncSetAttribute((const void*)mma_gemm<2, 64>,  cudaFuncAttributeMaxDynamicSharedMemorySize, SM64);

    // ---- spectral norms: batched repeated squaring + Rayleigh quotient ----
    split_W2<<<dim3(1024, 2), 256>>>(W_in, W_out);
    init_spec<<<1, 1024>>>();
    mma_gemm<2, 64><<<dim3(8, 16, 2), 256, SM64>>>(nullptr, nullptr, 0);   // G0 = W W^T (also stored)
    for (int k = 1; k <= NSQ; k++) {
        split_scaled<<<dim3(1024, 2), 256>>>(k - 1);
        mma_gemm<2, 64><<<dim3(8, 16, 2), 256, SM64>>>(nullptr, nullptr, k);
    }
    for (int r = 0; r < NMV; r++) {
        mv_kernel<<<dim3(64, 2), 256>>>();
        vnorm_kernel<<<2, 1024>>>();
    }
    rq_kernel<<<dim3(64, 2), 256>>>();
    fin_sigma<<<1, 32>>>();

    // ---- main path ----
    split_half<<<(BT * KDIM / 4 + 255) / 256, 256>>>(u, 0, 0, BT * KDIM / 4);
    split_half<<<(3072 * KDIM / 4 + 255) / 256, 256>>>(Wp, 1, 0, 3072 * KDIM / 4);
    split_half<<<(NN * KDIM / 4 + 255) / 256, 256>>>(W_in, 1, (size_t)3072 * KDIM, NN * KDIM / 4);
    split_half<<<(NN * KDIM / 4 + 255) / 256, 256>>>(W_out, 2, 0, NN * KDIM / 4);

    // GEMM1: raw = u @ [Wp ; W_in]^T  (+bp on Wp cols)
    mma_gemm<0, 128><<<dim3(NRAW / GBN, BT / 128), 256, SM128>>>(bp, nullptr, 0);

    ew_scan1<<<BB * NCHUNK * 8, 128>>>(alpha_log, delta_bias, log_gamma);
    scan_pass2<<<4, 1024>>>();
    scan_pass3<<<BB * NCHUNK * 8, 128>>>();

    // GEMM2: y = y_hat @ W_out^T * 1/(s0*s1)
    mma_gemm<1, 128><<<dim3(NN / GBN, BT / 128), 256, SM128>>>(nullptr, out, 0);
}

// round 7
// speedup vs baseline: 6.7108x; 1.0161x over previous
#include <cuda_runtime.h>
#include <cuda_fp16.h>
#include <math.h>
#include <stdint.h>

// Problem constants
#define BB   4
#define TT   4096
#define NN   1024
#define BT   16384
#define NRAW 4096
#define NCHUNK 32
#define LCHUNK 128

// GEMM tiling (HMMA mma.sync; tcgen05 unavailable: harness targets sm_103 w/o 'a')
#define GBN 128
#define GBK 64
#define KDIM 1024
#define KCH  16                          // KDIM/GBK

#define NSQ 7                            // squarings -> G^(2^NSQ)
#define NMV 5                            // chained matvecs

// stage = A(TBM*128B) + Bhi(16K) + Blo(16K); 3 stages
#define SM128 147456
#define SM64  122880

// ---------------------------------------------------------------------------
// Device scratch
// ---------------------------------------------------------------------------
__device__ __align__(128) float g_RAW[(size_t)BT * NRAW];
__device__ __align__(128) __half g_Ahi[(size_t)BT * KDIM];            // u (hi only)
__device__ __align__(128) __half g_Bhi[(size_t)NRAW * KDIM];          // [Wp(3072) ; W_in(1024)]
__device__ __align__(128) __half g_Blo[(size_t)NRAW * KDIM];
__device__ __align__(128) __half g_Whi[(size_t)NN * KDIM];            // W_out
__device__ __align__(128) __half g_Wlo[(size_t)NN * KDIM];
__device__ __align__(128) __half g_Yhi[(size_t)BT * NN];              // y_hat (hi only)
__device__ float g_AggA[BB * NCHUNK * NN];
__device__ float g_AggB[BB * NCHUNK * NN];
__device__ int   g_flag[BB * NCHUNK * 8];

// spectral-norm machinery (batched over both weights, index g in {0,1})
__device__ __align__(128) __half g_Shi[2 * 1024 * 1024];
__device__ __align__(128) __half g_Slo[2 * 1024 * 1024];
__device__ __align__(128) float g_Gk[2 * 1024 * 1024];
__device__ __align__(128) float g_G0[2 * 1024 * 1024];
__device__ float g_pv[2 * 1024];
__device__ float g_pw[2 * 1024];
__device__ float g_trace[32];            // [g*16 + step]
__device__ float g_acc[2];
__device__ float g_sigma[2];

// ---------------------------------------------------------------------------
// PTX helpers
// ---------------------------------------------------------------------------
__device__ __forceinline__ uint32_t smem_u32(const void* p) {
    uint32_t a;
    asm("{ .reg .u64 t; cvta.to.shared.u64 t, %1; cvt.u32.u64 %0, t; }" : "=r"(a) : "l"(p));
    return a;
}

#define CP_ASYNC16(dst, src) \
    asm volatile("cp.async.cg.shared.global [%0], [%1], 16;" :: "r"(dst), "l"(src))
#define CP_COMMIT() asm volatile("cp.async.commit_group;" ::: "memory")
#define CP_WAIT1()  asm volatile("cp.async.wait_group 1;" ::: "memory")
#define CP_WAIT0()  asm volatile("cp.async.wait_group 0;" ::: "memory")

#define LDMATRIX_X4(r0, r1, r2, r3, addr) \
    asm volatile("ldmatrix.sync.aligned.m8n8.x4.shared.b16 {%0,%1,%2,%3}, [%4];" \
                 : "=r"(r0), "=r"(r1), "=r"(r2), "=r"(r3) : "r"(addr))

#define MMA_FP16(d, a, b) \
    asm volatile("mma.sync.aligned.m16n8k16.row.col.f32.f16.f16.f32 " \
        "{%0,%1,%2,%3}, {%4,%5,%6,%7}, {%8,%9}, {%0,%1,%2,%3};" \
        : "+f"((d)[0]), "+f"((d)[1]), "+f"((d)[2]), "+f"((d)[3]) \
        : "r"((a)[0]), "r"((a)[1]), "r"((a)[2]), "r"((a)[3]), "r"((b)[0]), "r"((b)[1]))

// ---------------------------------------------------------------------------
// fp16 hi/lo split helpers
// ---------------------------------------------------------------------------
__device__ __forceinline__ void split4h(const float4 v, uint2& H, uint2& L) {
    union { __half b[4]; uint2 u; } h, l;
    float x[4] = {v.x, v.y, v.z, v.w};
    #pragma unroll
    for (int j = 0; j < 4; j++) {
        __half hb = __float2half_rn(x[j]);
        h.b[j] = hb;
        l.b[j] = __float2half_rn(x[j] - __half2float(hb));
    }
    H = h.u; L = l.u;
}
__device__ __forceinline__ uint2 hi4h(const float4 v) {
    union { __half b[4]; uint2 u; } h;
    h.b[0] = __float2half_rn(v.x); h.b[1] = __float2half_rn(v.y);
    h.b[2] = __float2half_rn(v.z); h.b[3] = __float2half_rn(v.w);
    return h.u;
}

// All input splits in ONE launch (block-range dispatch).
// seg0 u->Ahi [0,16384); seg1 Wp->B [16384,19456); seg2 W_in->B+786432 [19456,20480);
// seg3 W_out->W [20480,21504); seg4 W_in->S[g=0] [21504,22528); seg5 W_out->S[g=1] [22528,23552)
__global__ void __launch_bounds__(256) split_all(
    const float* __restrict__ u, const float* __restrict__ Wp,
    const float* __restrict__ Win, const float* __restrict__ Wout)
{
    int blk = blockIdx.x, tid = threadIdx.x;
    if (blk < 16384) {
        int i = blk * 256 + tid;
        ((uint2*)g_Ahi)[i] = hi4h(((const float4*)u)[i]);
    } else if (blk < 19456) {
        int i = (blk - 16384) * 256 + tid;
        uint2 H, L; split4h(((const float4*)Wp)[i], H, L);
        ((uint2*)g_Bhi)[i] = H; ((uint2*)g_Blo)[i] = L;
    } else if (blk < 20480) {
        int i = (blk - 19456) * 256 + tid;
        uint2 H, L; split4h(((const float4*)Win)[i], H, L);
        ((uint2*)g_Bhi)[786432 + i] = H; ((uint2*)g_Blo)[786432 + i] = L;
    } else if (blk < 21504) {
        int i = (blk - 20480) * 256 + tid;
        uint2 H, L; split4h(((const float4*)Wout)[i], H, L);
        ((uint2*)g_Whi)[i] = H; ((uint2*)g_Wlo)[i] = L;
    } else if (blk < 22528) {
        int i = (blk - 21504) * 256 + tid;
        uint2 H, L; split4h(((const float4*)Win)[i], H, L);
        ((uint2*)g_Shi)[i] = H; ((uint2*)g_Slo)[i] = L;
    } else {
        int i = (blk - 22528) * 256 + tid;
        uint2 H, L; split4h(((const float4*)Wout)[i], H, L);
        ((uint2*)g_Shi)[262144 + i] = H; ((uint2*)g_Slo)[262144 + i] = L;
    }
}

// g_Gk[g] * (1024/trace[g][step]) -> g_Shi/Slo[g]
__global__ void __launch_bounds__(256) split_scaled(int step) {
    int g = blockIdx.y;
    int i = blockIdx.x * 256 + threadIdx.x;
    float s = 1024.0f / g_trace[g * 16 + step];
    float4 v = ((const float4*)(g_Gk + (size_t)g * 1048576))[i];
    v.x *= s; v.y *= s; v.z *= s; v.w *= s;
    uint2 H, L;
    split4h(v, H, L);
    ((uint2*)(g_Shi + (size_t)g * 1048576))[i] = H;
    ((uint2*)(g_Slo + (size_t)g * 1048576))[i] = L;
}

__global__ void __launch_bounds__(1024) init_spec() {
    int t = threadIdx.x;
    float v = 0.5f + __sinf((float)t * 0.7311f);
    g_pv[t] = v;
    g_pv[1024 + t] = v;
    g_flag[t] = 0;                       // lookback flags (graph-replay reset)
    if (t < 32) g_trace[t] = 0.f;
    if (t < 2) g_acc[t] = 0.f;
}

// ---------------------------------------------------------------------------
// Small matvec helpers (batched over g)
// ---------------------------------------------------------------------------
__global__ void __launch_bounds__(256) mv_kernel() {
    int g = blockIdx.y;
    const float* G = g_Gk + (size_t)g * 1048576;
    const float4* V4 = (const float4*)(g_pv + g * 1024);
    int w = threadIdx.x >> 5, lane = threadIdx.x & 31;
    #pragma unroll
    for (int rr = 0; rr < 2; rr++) {
        int r = blockIdx.x * 16 + w * 2 + rr;
        const float4* Gr = (const float4*)(G + (size_t)r * 1024);
        float s = 0.f;
        #pragma unroll 4
        for (int j = lane; j < 256; j += 32) {
            float4 a = Gr[j], x = V4[j];
            s += a.x * x.x + a.y * x.y + a.z * x.z + a.w * x.w;
        }
        #pragma unroll
        for (int o = 16; o > 0; o >>= 1) s += __shfl_xor_sync(0xffffffffu, s, o);
        if (lane == 0) g_pw[g * 1024 + r] = s;
    }
}

__global__ void __launch_bounds__(1024) vnorm_kernel() {
    __shared__ float sp[32];
    int g = blockIdx.x;
    int t = threadIdx.x, lane = t & 31, w = t >> 5;
    float v = g_pw[g * 1024 + t];
    float p = v * v;
    #pragma unroll
    for (int o = 16; o > 0; o >>= 1) p += __shfl_xor_sync(0xffffffffu, p, o);
    if (lane == 0) sp[w] = p;
    __syncthreads();
    if (w == 0) {
        float q = sp[lane];
        #pragma unroll
        for (int o = 16; o > 0; o >>= 1) q += __shfl_xor_sync(0xffffffffu, q, o);
        if (lane == 0) sp[0] = rsqrtf(q);
    }
    __syncthreads();
    g_pv[g * 1024 + t] = v * sp[0];
}

// Rayleigh quotient v^T G0 v  (v unit) -> g_acc[g]
__global__ void __launch_bounds__(256) rq_kernel() {
    int g = blockIdx.y;
    const float* G0 = g_G0 + (size_t)g * 1048576;
    const float4* V4 = (const float4*)(g_pv + g * 1024);
    int w = threadIdx.x >> 5, lane = threadIdx.x & 31;
    float part = 0.f;
    #pragma unroll
    for (int rr = 0; rr < 2; rr++) {
        int r = blockIdx.x * 16 + w * 2 + rr;
        const float4* Gr = (const float4*)(G0 + (size_t)r * 1024);
        float s = 0.f;
        #pragma unroll 4
        for (int j = lane; j < 256; j += 32) {
            float4 a = Gr[j], x = V4[j];
            s += a.x * x.x + a.y * x.y + a.z * x.z + a.w * x.w;
        }
        #pragma unroll
        for (int o = 16; o > 0; o >>= 1) s += __shfl_xor_sync(0xffffffffu, s, o);
        if (lane == 0) part += s * g_pv[g * 1024 + r];
    }
    if (lane == 0) atomicAdd(&g_acc[g], part);
}

__global__ void fin_sigma() {
    if (threadIdx.x < 2)
        g_sigma[threadIdx.x] = fmaxf(1.0f, sqrtf(fmaxf(g_acc[threadIdx.x], 0.f)));
}

// ---------------------------------------------------------------------------
// HMMA GEMM (NT), fp16 2-term split: C = Ahi*Bhi + Ahi*Blo
// TBM x 128 x 64 tiles, 8 warps (4m x 2n), 3-stage cp.async pipeline.
// MODE 0: A=g_Ahi,  B=g_Bhi/lo, C=g_RAW (ldc 4096), +bias for col<3072
// MODE 1: A=g_Yhi,  B=g_Whi/lo, C=out (ldc 1024), * 1/(s0*s1)
// MODE 2: A=g_Shi[z], B=g_Shi/lo[z], C=g_Gk[z] (+g_G0 when step==0),
//         trace -> g_trace[z*16+step]
// ---------------------------------------------------------------------------
template <int TBM>
__device__ __forceinline__ void load_tiles(
    uint32_t base,
    const __half* __restrict__ Ah,
    const __half* __restrict__ Bh, const __half* __restrict__ Bl,
    int tid)
{
    constexpr uint32_t AB = TBM * 128;
    uint32_t sA = base, sBhi = base + AB, sBlo = base + AB + 16384;
    #pragma unroll
    for (int it = 0; it < TBM / 32; it++) {
        int idx = tid + it * 256;
        int r = idx >> 3, c8 = idx & 7;
        uint32_t sw = (uint32_t)r * 128 + (((uint32_t)c8 * 16) ^ (((uint32_t)r & 7) << 4));
        CP_ASYNC16(sA + sw, (const char*)(Ah + (size_t)r * KDIM) + c8 * 16);
    }
    #pragma unroll
    for (int it = 0; it < 4; it++) {
        int idx = tid + it * 256;
        int r = idx >> 3, c8 = idx & 7;
        uint32_t sw = (uint32_t)r * 128 + (((uint32_t)c8 * 16) ^ (((uint32_t)r & 7) << 4));
        CP_ASYNC16(sBhi + sw, (const char*)(Bh + (size_t)r * KDIM) + c8 * 16);
        CP_ASYNC16(sBlo + sw, (const char*)(Bl + (size_t)r * KDIM) + c8 * 16);
    }
}

template <int MODE, int TBM>
__global__ void __launch_bounds__(256, 1) mma_gemm(
    const float* __restrict__ bias, float* __restrict__ Cout, int step)
{
    constexpr int MT = TBM / 64;
    constexpr uint32_t AB = TBM * 128;
    constexpr uint32_t STAGE = AB + 32768;
    extern __shared__ char smem[];
    uint32_t sb = smem_u32(smem);
    int tid = threadIdx.x, wid = tid >> 5, lane = tid & 31;
    int m0 = blockIdx.y * TBM;
    int n0 = blockIdx.x * GBN;
    int wm = wid >> 1, wn = wid & 1;
    int m_off = wm * (TBM / 4), n_off = wn * 64;

    size_t goff = (MODE == 2) ? (size_t)blockIdx.z * 1048576 : 0;
    const __half* Ah = (MODE == 0 ? g_Ahi : MODE == 1 ? g_Yhi : g_Shi) + goff + (size_t)m0 * KDIM;
    const __half* Bh = (MODE == 0 ? g_Bhi : MODE == 1 ? g_Whi : g_Shi) + goff + (size_t)n0 * KDIM;
    const __half* Bl = (MODE == 0 ? g_Blo : MODE == 1 ? g_Wlo : g_Slo) + goff + (size_t)n0 * KDIM;
    float* C = (MODE == 0) ? g_RAW : (MODE == 1) ? Cout : (g_Gk + goff);
    const int ldc = (MODE == 0) ? NRAW : NN;

    float acc[MT][8][4];
    #pragma unroll
    for (int mt = 0; mt < MT; mt++)
        #pragma unroll
        for (int n = 0; n < 8; n++)
            #pragma unroll
            for (int j = 0; j < 4; j++) acc[mt][n][j] = 0.f;

    int lrow = lane & 15;
    uint32_t lcol = ((uint32_t)(lane >> 4)) << 4;

    load_tiles<TBM>(sb,         Ah,      Bh,      Bl,      tid); CP_COMMIT();
    load_tiles<TBM>(sb + STAGE, Ah + 64, Bh + 64, Bl + 64, tid); CP_COMMIT();

    for (int ch = 0; ch < KCH; ch++) {
        if (ch == KCH - 1) { CP_WAIT0(); } else { CP_WAIT1(); }
        __syncthreads();
        if (ch + 2 < KCH) {
            int k0 = (ch + 2) * GBK;
            load_tiles<TBM>(sb + ((ch + 2) % 3) * STAGE, Ah + k0, Bh + k0, Bl + k0, tid);
            CP_COMMIT();
        }
        uint32_t base = sb + (ch % 3) * STAGE;
        #pragma unroll
        for (int ks = 0; ks < 4; ks++) {
            uint32_t cb = (uint32_t)ks * 32 + lcol;
            uint32_t ahi[MT][4];
            #pragma unroll
            for (int mt = 0; mt < MT; mt++) {
                int row = m_off + mt * 16 + lrow;
                uint32_t ad = base + (uint32_t)row * 128 + (cb ^ (((uint32_t)row & 7) << 4));
                LDMATRIX_X4(ahi[mt][0], ahi[mt][1], ahi[mt][2], ahi[mt][3], ad);
            }
            uint32_t bhi[8][2], blo[8][2];
            #pragma unroll
            for (int nt = 0; nt < 4; nt++) {
                int row = n_off + nt * 16 + lrow;
                uint32_t bd = base + AB + (uint32_t)row * 128 + (cb ^ (((uint32_t)row & 7) << 4));
                uint32_t r0, r1, r2, r3;
                LDMATRIX_X4(r0, r1, r2, r3, bd);
                bhi[nt * 2][0] = r0; bhi[nt * 2][1] = r2;
                bhi[nt * 2 + 1][0] = r1; bhi[nt * 2 + 1][1] = r3;
                LDMATRIX_X4(r0, r1, r2, r3, bd + 16384);
                blo[nt * 2][0] = r0; blo[nt * 2][1] = r2;
                blo[nt * 2 + 1][0] = r1; blo[nt * 2 + 1][1] = r3;
            }
            #pragma unroll
            for (int mt = 0; mt < MT; mt++)
                #pragma unroll
                for (int n = 0; n < 8; n++) {
                    MMA_FP16(acc[mt][n], ahi[mt], bhi[n]);
                    MMA_FP16(acc[mt][n], ahi[mt], blo[n]);
                }
        }
    }

    float scale = 1.0f;
    if (MODE == 1) scale = 1.0f / (g_sigma[0] * g_sigma[1]);
    int gid = lane >> 2, tig = lane & 3;
    float tp = 0.f;
    bool diag = (MODE == 2) && (m0 < n0 + GBN) && (n0 < m0 + TBM);

    #pragma unroll
    for (int mt = 0; mt < MT; mt++) {
        #pragma unroll
        for (int n = 0; n < 8; n++) {
            int col = n0 + n_off + n * 8 + tig * 2;
            int r0 = m0 + m_off + mt * 16 + gid;
            float2 v0 = make_float2(acc[mt][n][0], acc[mt][n][1]);
            float2 v1 = make_float2(acc[mt][n][2], acc[mt][n][3]);
            if (MODE == 0) {
                if (col < 3072) {
                    float b0 = __ldg(&bias[col]), b1 = __ldg(&bias[col + 1]);
                    v0.x += b0; v0.y += b1; v1.x += b0; v1.y += b1;
                }
            } else if (MODE == 1) {
                v0.x *= scale; v0.y *= scale; v1.x *= scale; v1.y *= scale;
            } else if (diag) {
                if (r0 == col)         tp += v0.x;
                if (r0 == col + 1)     tp += v0.y;
                if (r0 + 8 == col)     tp += v1.x;
                if (r0 + 8 == col + 1) tp += v1.y;
            }
            *(float2*)(C + (size_t)r0 * ldc + col) = v0;
            *(float2*)(C + (size_t)(r0 + 8) * ldc + col) = v1;
            if (MODE == 2 && step == 0) {
                float* C0 = g_G0 + goff;
                *(float2*)(C0 + (size_t)r0 * ldc + col) = v0;
                *(float2*)(C0 + (size_t)(r0 + 8) * ldc + col) = v1;
            }
        }
    }
    if (MODE == 2 && diag && tp != 0.f)
        atomicAdd(&g_trace[blockIdx.z * 16 + step], tp);
}

// ---------------------------------------------------------------------------
// Single-pass scan with decoupled lookback.
// sweep1: transform + chunk aggregates; publish; lookback for z0; sweep2: emit Yhi.
// grid = BB*NCHUNK*8 = 1024 blocks x 128 thr (all co-resident -> no deadlock).
// ---------------------------------------------------------------------------
__device__ __forceinline__ float softplus_f(float x) {
    return fmaxf(x, 0.f) + log1pf(expf(-fabsf(x)));
}
__device__ __forceinline__ float tanh_fast(float x) {
    const float L2E2 = 2.8853900817779268f;
    float ax = fabsf(x);
    float e = exp2f(ax * L2E2);
    float r = 1.0f - 2.0f / (e + 1.0f);
    return copysignf(r, x);
}
__device__ __forceinline__ void xform_ab(float dr, float brw, float alpha, float db,
                                         float gamma, float gg, float& a, float& bu,
                                         float crw, float& cv, bool need_c) {
    const float L2E = 1.4426950408889634f;
    float s  = dr + db;
    float t1 = exp2f(s * L2E);
    float Lg = log2f(1.0f + t1);
    a = fminf(exp2f(-alpha * Lg), 1.0f - 1e-4f);
    float bv = tanh_fast(brw);
    cv = need_c ? tanh_fast(crw) : 0.f;
    float p  = a * a + cv * cv;              // note: sweep1 passes real crw too
    float r2 = bv * bv;
    float q  = a * bv;
    float d1 = p - r2;
    float disc = fmaf(d1, d1, 4.0f * q * q) + 1e-12f;
    float sq   = disc * rsqrtf(disc);
    float lam  = 0.5f * (p + r2 + sq) + 1e-12f;
    float inv  = rsqrtf(fmaxf(lam, 1.0f));
    a  *= inv;
    bu  = bv * inv * gamma * gg;
    cv *= inv;
}

__global__ void __launch_bounds__(128) sp_scan(
    const float* __restrict__ alpha_log, const float* __restrict__ delta_bias,
    const float* __restrict__ log_gamma)
{
    int bid = blockIdx.x;                 // b*256 + chunk*8 + cb
    int cb = bid & 7;
    int chunk = (bid >> 3) & 31;
    int b = bid >> 8;
    int tid = threadIdx.x;
    int i = cb * 128 + tid;
    size_t base = ((size_t)(b * TT + chunk * LCHUNK)) * NRAW + i;

    float alpha = softplus_f(alpha_log[i]);
    float db    = delta_bias[i];
    float gamma = expf(log_gamma[0]);

    // sweep1: aggregates (c IS needed: spectral normalization uses c)
    float A = 1.f, Bc = 0.f;
    for (int t = 0; t < LCHUNK; t++) {
        size_t o = base + (size_t)t * NRAW;
        float dr  = g_RAW[o];
        float brw = g_RAW[o + 1024];
        float crw = g_RAW[o + 2048];
        float gg  = g_RAW[o + 3072];
        float a, bu, cv;
        xform_ab(dr, brw, alpha, db, gamma, gg, a, bu, crw, cv, true);
        Bc = fmaf(a, Bc, bu);
        A *= a;
    }
    int ai = (b * NCHUNK + chunk) * NN + i;
    g_AggA[ai] = A;
    g_AggB[ai] = Bc;
    __threadfence();
    __syncthreads();
    if (tid == 0) atomicExch(&g_flag[bid], 1);

    // lookback: z0 = scan of chunks 0..chunk-1 applied to 0
    float Aa = 1.f, Ba = 0.f;
    for (int p = chunk - 1; p >= 0; p--) {
        int pbid = b * 256 + p * 8 + cb;
        if (tid == 0) {
            while (atomicAdd(&g_flag[pbid], 0) == 0) { }
        }
        __syncthreads();
        int pai = (b * NCHUNK + p) * NN + i;
        float Ap = __ldcg(&g_AggA[pai]);
        float Bp = __ldcg(&g_AggB[pai]);
        Ba = fmaf(Aa, Bp, Ba);              // acc = acc ∘ f_p (f_p applied first)
        Aa = Aa * Ap;
    }
    float z = Ba;

    // sweep2: emit y_hat = c_t * z_t (state before step t)
    int bt0 = b * TT + chunk * LCHUNK;
    for (int t = 0; t < LCHUNK; t++) {
        size_t o = base + (size_t)t * NRAW;
        float dr  = g_RAW[o];
        float brw = g_RAW[o + 1024];
        float crw = g_RAW[o + 2048];
        float gg  = g_RAW[o + 3072];
        float a, bu, cv;
        xform_ab(dr, brw, alpha, db, gamma, gg, a, bu, crw, cv, true);
        g_Yhi[(size_t)(bt0 + t) * NN + i] = __float2half_rn(cv * z);
        z = fmaf(a, z, bu);
    }
}

// ---------------------------------------------------------------------------
// Launch
// ---------------------------------------------------------------------------
extern "C" void kernel_launch(void* const* d_in, const int* in_sizes, int n_in,
                              void* d_out, int out_size)
{
    (void)in_sizes; (void)n_in; (void)out_size;
    const float* u          = (const float*)d_in[0];
    const float* W_in       = (const float*)d_in[1];
    const float* W_out      = (const float*)d_in[2];
    const float* Wp         = (const float*)d_in[3];
    const float* bp         = (const float*)d_in[4];
    const float* alpha_log  = (const float*)d_in[5];
    const float* delta_bias = (const float*)d_in[6];
    const float* log_gamma  = (const float*)d_in[7];
    float* out = (float*)d_out;

    cudaFuncSetAttribute((const void*)mma_gemm<0, 128>, cudaFuncAttributeMaxDynamicSharedMemorySize, SM128);
    cudaFuncSetAttribute((const void*)mma_gemm<1, 128>, cudaFuncAttributeMaxDynamicSharedMemorySize, SM128);
    cudaFuncSetAttribute((const void*)mma_gemm<2, 64>,  cudaFuncAttributeMaxDynamicSharedMemorySize, SM64);

    // ---- one fused split launch (A, B, W, S) + spec init ----
    split_all<<<23552, 256>>>(u, Wp, W_in, W_out);
    init_spec<<<1, 1024>>>();

    // ---- spectral norms: batched repeated squaring + Rayleigh quotient ----
    mma_gemm<2, 64><<<dim3(8, 16, 2), 256, SM64>>>(nullptr, nullptr, 0);   // G0 = W W^T (stored)
    for (int k = 1; k <= NSQ; k++) {
        split_scaled<<<dim3(1024, 2), 256>>>(k - 1);
        mma_gemm<2, 64><<<dim3(8, 16, 2), 256, SM64>>>(nullptr, nullptr, k);
    }
    for (int r = 0; r < NMV; r++) {
        mv_kernel<<<dim3(64, 2), 256>>>();
        vnorm_kernel<<<2, 1024>>>();
    }
    rq_kernel<<<dim3(64, 2), 256>>>();
    fin_sigma<<<1, 32>>>();

    // ---- main path ----
    // GEMM1: raw = u @ [Wp ; W_in]^T  (+bp on Wp cols)
    mma_gemm<0, 128><<<dim3(NRAW / GBN, BT / 128), 256, SM128>>>(bp, nullptr, 0);

    // fused elementwise + full scan (decoupled lookback), emits Yhi
    sp_scan<<<BB * NCHUNK * 8, 128>>>(alpha_log, delta_bias, log_gamma);

    // GEMM2: y = y_hat @ W_out^T * 1/(s0*s1)
    mma_gemm<1, 128><<<dim3(NN / GBN, BT / 128), 256, SM128>>>(nullptr, out, 0);
}